// round 1
// baseline (speedup 1.0000x reference)
#include <cuda_runtime.h>
#include <math.h>

// Problem constants
#define BB 2
#define TT 2048
#define CC 2048
#define NH 16
#define HSD 128
#define DL 1024

// ---------------------------------------------------------------------------
// Scratch (no cudaMalloc allowed)
// ---------------------------------------------------------------------------
__device__ float g_q[BB * TT * CC];
__device__ float g_c[BB * TT * DL];
__device__ float g_k[BB * TT * CC];
__device__ float g_v[BB * TT * CC];
__device__ float g_y[BB * TT * CC];

// ---------------------------------------------------------------------------
// SGEMM: C[M,N] = A[M,K] @ B[K,N] (+bias). 128x128 tile, BK=16, 256 threads,
// 8x8 per-thread microtile. M,N multiples of 128; K multiple of 16.
// ---------------------------------------------------------------------------
#define GBM 128
#define GBN 128
#define GBK 16

__global__ __launch_bounds__(256, 2) void sgemm_kernel(
    const float* __restrict__ A, const float* __restrict__ B,
    float* __restrict__ C, int M, int N, int K,
    const float* __restrict__ bias)
{
    __shared__ float As[GBK][GBM];   // stored k-major (transposed A tile)
    __shared__ float Bs[GBK][GBN];

    const int tid = threadIdx.x;
    const int tx = tid & 15;         // 0..15 -> N direction
    const int ty = tid >> 4;         // 0..15 -> M direction
    const int bm = blockIdx.y * GBM;
    const int bn = blockIdx.x * GBN;

    const float* Ab = A + (size_t)bm * K;
    const float* Bb = B + bn;

    float acc[8][8];
    #pragma unroll
    for (int i = 0; i < 8; i++)
        #pragma unroll
        for (int j = 0; j < 8; j++) acc[i][j] = 0.f;

    for (int kt = 0; kt < K; kt += GBK) {
        // Load A tile (128x16) and B tile (16x128), 2 float4 each per thread
        #pragma unroll
        for (int l = 0; l < 2; l++) {
            int s = tid + l * 256;
            // A: slot -> row = s/4, k = (s%4)*4
            int ar = s >> 2, ak = (s & 3) << 2;
            float4 av = *reinterpret_cast<const float4*>(
                Ab + (size_t)ar * K + kt + ak);
            As[ak + 0][ar] = av.x;
            As[ak + 1][ar] = av.y;
            As[ak + 2][ar] = av.z;
            As[ak + 3][ar] = av.w;
            // B: slot -> k = s/32, n = (s%32)*4
            int br = s >> 5, bc = (s & 31) << 2;
            *reinterpret_cast<float4*>(&Bs[br][bc]) =
                *reinterpret_cast<const float4*>(
                    Bb + (size_t)(kt + br) * N + bc);
        }
        __syncthreads();

        #pragma unroll
        for (int kk = 0; kk < GBK; kk++) {
            float a[8], b[8];
            #pragma unroll
            for (int i = 0; i < 8; i++) a[i] = As[kk][ty * 8 + i];
            #pragma unroll
            for (int j = 0; j < 8; j++) b[j] = Bs[kk][tx * 8 + j];
            #pragma unroll
            for (int i = 0; i < 8; i++)
                #pragma unroll
                for (int j = 0; j < 8; j++)
                    acc[i][j] += a[i] * b[j];
        }
        __syncthreads();
    }

    // Epilogue
    #pragma unroll
    for (int i = 0; i < 8; i++) {
        int row = bm + ty * 8 + i;
        float* Crow = C + (size_t)row * N + bn + tx * 8;
        #pragma unroll
        for (int j = 0; j < 8; j += 4) {
            float4 v;
            v.x = acc[i][j + 0];
            v.y = acc[i][j + 1];
            v.z = acc[i][j + 2];
            v.w = acc[i][j + 3];
            if (bias) {
                const float* bp = bias + bn + tx * 8 + j;
                v.x += bp[0]; v.y += bp[1]; v.z += bp[2]; v.w += bp[3];
            }
            *reinterpret_cast<float4*>(Crow + j) = v;
        }
    }
}

// ---------------------------------------------------------------------------
// Flash attention (causal): per (query-block qb, head h, batch b).
// Br=Bc=64, HS=128. 256 threads: thread t -> row i = t&63, group g = t>>6
// (g selects 16-col slice for S, 32-col slice for O).
// ---------------------------------------------------------------------------
#define FBR 64
#define FBC 64
#define QST 132     // smem row stride for Q/K/V tiles (conflict-free float4)
#define PST 65      // smem row stride for P tile

__global__ __launch_bounds__(256) void flash_kernel(
    const float* __restrict__ Q, const float* __restrict__ K,
    const float* __restrict__ V, float* __restrict__ Y)
{
    extern __shared__ float sm[];
    float* Qs  = sm;                       // 64*132
    float* Ks  = Qs + FBR * QST;           // 64*132
    float* Vs  = Ks + FBC * QST;           // 64*132
    float* Ps  = Vs + FBC * QST;           // 64*65
    float* red = Ps + FBR * PST;           // 512: [0..255]=pmax, [256..511]=psum

    const int qb  = blockIdx.x;
    const int h   = blockIdx.y;
    const int b   = blockIdx.z;
    const int tid = threadIdx.x;
    const int i   = tid & 63;
    const int g   = tid >> 6;

    const float scale = 0.08838834764831845f;  // 1/sqrt(128)

    // Load Q tile
    const size_t baseQ = ((size_t)(b * TT + qb * FBR)) * CC + h * HSD;
    for (int s = tid; s < FBR * HSD / 4; s += 256) {
        int r = s >> 5, c4 = (s & 31) << 2;
        *reinterpret_cast<float4*>(&Qs[r * QST + c4]) =
            *reinterpret_cast<const float4*>(Q + baseQ + (size_t)r * CC + c4);
    }

    float m_i = -1e30f, l_i = 0.f;
    float o[32];
    #pragma unroll
    for (int c = 0; c < 32; c++) o[c] = 0.f;

    for (int kb = 0; kb <= qb; kb++) {
        __syncthreads();   // protects Ks/Vs/red reuse; also Q visibility on kb=0
        const size_t baseK = ((size_t)(b * TT + kb * FBC)) * CC + h * HSD;
        for (int s = tid; s < FBC * HSD / 4; s += 256) {
            int r = s >> 5, c4 = (s & 31) << 2;
            *reinterpret_cast<float4*>(&Ks[r * QST + c4]) =
                *reinterpret_cast<const float4*>(K + baseK + (size_t)r * CC + c4);
            *reinterpret_cast<float4*>(&Vs[r * QST + c4]) =
                *reinterpret_cast<const float4*>(V + baseK + (size_t)r * CC + c4);
        }
        __syncthreads();

        // ---- Phase A: S[i][g*16 .. g*16+15] = Q[i,:] . K[j,:] ----
        float sreg[16];
        #pragma unroll
        for (int jj = 0; jj < 16; jj++) sreg[jj] = 0.f;

        for (int k4 = 0; k4 < HSD; k4 += 4) {
            float4 q4 = *reinterpret_cast<const float4*>(&Qs[i * QST + k4]);
            #pragma unroll
            for (int jj = 0; jj < 16; jj++) {
                float4 kv = *reinterpret_cast<const float4*>(
                    &Ks[(g * 16 + jj) * QST + k4]);
                sreg[jj] += q4.x * kv.x + q4.y * kv.y + q4.z * kv.z + q4.w * kv.w;
            }
        }

        // ---- scale + causal mask + local max ----
        float mx = -1e30f;
        const bool diag = (kb == qb);
        #pragma unroll
        for (int jj = 0; jj < 16; jj++) {
            float s = sreg[jj] * scale;
            if (diag && (g * 16 + jj) > i) s = -1e30f;
            sreg[jj] = s;
            mx = fmaxf(mx, s);
        }
        red[g * 64 + i] = mx;
        __syncthreads();

        float m_new = m_i;
        #pragma unroll
        for (int gg = 0; gg < 4; gg++) m_new = fmaxf(m_new, red[gg * 64 + i]);
        float alpha = __expf(m_i - m_new);

        float lsum = 0.f;
        #pragma unroll
        for (int jj = 0; jj < 16; jj++) {
            float p = __expf(sreg[jj] - m_new);
            Ps[i * PST + g * 16 + jj] = p;
            lsum += p;
        }
        red[256 + g * 64 + i] = lsum;
        __syncthreads();

        float ltot = 0.f;
        #pragma unroll
        for (int gg = 0; gg < 4; gg++) ltot += red[256 + gg * 64 + i];
        l_i = l_i * alpha + ltot;
        m_i = m_new;

        #pragma unroll
        for (int c = 0; c < 32; c++) o[c] *= alpha;

        // ---- Phase C: O[i][g*32 .. +31] += P[i,:] @ V[:, cols] ----
        for (int j = 0; j < FBC; j++) {
            float p = Ps[i * PST + j];
            const float* vrow = &Vs[j * QST + g * 32];
            #pragma unroll
            for (int c4 = 0; c4 < 32; c4 += 4) {
                float4 vv = *reinterpret_cast<const float4*>(vrow + c4);
                o[c4 + 0] += p * vv.x;
                o[c4 + 1] += p * vv.y;
                o[c4 + 2] += p * vv.z;
                o[c4 + 3] += p * vv.w;
            }
        }
    }

    // ---- normalize + write ----
    float inv_l = 1.0f / l_i;
    const size_t baseY =
        ((size_t)(b * TT + qb * FBR + i)) * CC + h * HSD + g * 32;
    #pragma unroll
    for (int c4 = 0; c4 < 32; c4 += 4) {
        float4 v;
        v.x = o[c4 + 0] * inv_l;
        v.y = o[c4 + 1] * inv_l;
        v.z = o[c4 + 2] * inv_l;
        v.w = o[c4 + 3] * inv_l;
        *reinterpret_cast<float4*>(g_y + 0) ; // no-op guard removed below
        *reinterpret_cast<float4*>((float*)Y + baseY + c4) = v;
    }
}

// ---------------------------------------------------------------------------
// Launch
// ---------------------------------------------------------------------------
extern "C" void kernel_launch(void* const* d_in, const int* in_sizes, int n_in,
                              void* d_out, int out_size)
{
    (void)in_sizes; (void)n_in; (void)out_size;
    const float* x  = (const float*)d_in[0];
    const float* Wq = (const float*)d_in[1];
    const float* Wc = (const float*)d_in[2];
    const float* Wk = (const float*)d_in[3];
    const float* Wv = (const float*)d_in[4];
    const float* Wo = (const float*)d_in[5];
    const float* bo = (const float*)d_in[6];
    float* out = (float*)d_out;

    float *q, *c, *k, *v, *y;
    cudaGetSymbolAddress((void**)&q, g_q);
    cudaGetSymbolAddress((void**)&c, g_c);
    cudaGetSymbolAddress((void**)&k, g_k);
    cudaGetSymbolAddress((void**)&v, g_v);
    cudaGetSymbolAddress((void**)&y, g_y);

    const int M = BB * TT;   // 4096

    dim3 blk(256);

    // q = x @ Wq   (4096 x 2048 x 2048)
    sgemm_kernel<<<dim3(CC / GBN, M / GBM), blk>>>(x, Wq, q, M, CC, CC, nullptr);
    // c = x @ Wc   (4096 x 1024 x 2048)
    sgemm_kernel<<<dim3(DL / GBN, M / GBM), blk>>>(x, Wc, c, M, DL, CC, nullptr);
    // k = c @ Wk   (4096 x 2048 x 1024)
    sgemm_kernel<<<dim3(CC / GBN, M / GBM), blk>>>(c, Wk, k, M, CC, DL, nullptr);
    // v = c @ Wv
    sgemm_kernel<<<dim3(CC / GBN, M / GBM), blk>>>(c, Wv, v, M, CC, DL, nullptr);

    // flash attention: grid (T/64, H, B)
    size_t smem = (size_t)(3 * FBR * QST + FBR * PST + 512) * sizeof(float);
    cudaFuncSetAttribute(flash_kernel,
                         cudaFuncAttributeMaxDynamicSharedMemorySize,
                         (int)smem);
    flash_kernel<<<dim3(TT / FBR, NH, BB), blk, smem>>>(q, k, v, y);

    // out = y @ Wo + bo
    sgemm_kernel<<<dim3(CC / GBN, M / GBM), blk>>>(y, Wo, out, M, CC, CC, bo);
}

// round 6
// speedup vs baseline: 3.1055x; 3.1055x over previous
#include <cuda_runtime.h>
#include <cstdint>

// ---------------------------------------------------------------------------
// Problem constants
// ---------------------------------------------------------------------------
#define BB 2
#define TT 2048
#define CC 2048
#define NH 16
#define HSD 128
#define DL 1024
#define BT (BB * TT)      // 4096
#define BHN (BB * NH)     // 32

// ---------------------------------------------------------------------------
// Scratch (__device__ globals; no cudaMalloc allowed)
// ---------------------------------------------------------------------------
__device__ float g_q[BT * CC];
__device__ float g_c[BT * DL];
__device__ float g_k[BT * CC];
__device__ float g_vt[CC * BT];         // v transposed: [C][B*T]
__device__ float g_y[BT * CC];
__device__ float g_s[134217728];        // 512MB scores: [BH][T][T]
__device__ float g_wqt[CC * CC];
__device__ float g_wct[DL * CC];
__device__ float g_wkt[CC * DL];
__device__ float g_wvt[CC * DL];
__device__ float g_wot[CC * CC];

// ---------------------------------------------------------------------------
// Helpers (portable PTX only: cp.async + mma.sync tf32, all sm_80+)
// ---------------------------------------------------------------------------
__device__ __forceinline__ uint32_t smem_u32(const void* p) {
    uint32_t a;
    asm("{ .reg .u64 t; cvta.to.shared.u64 t, %1; cvt.u32.u64 %0, t; }"
        : "=r"(a) : "l"(p));
    return a;
}

__device__ __forceinline__ void cp_async16(uint32_t dst, const void* src) {
    asm volatile("cp.async.cg.shared.global [%0], [%1], 16;"
                 :: "r"(dst), "l"(src));
}
#define CP_COMMIT() asm volatile("cp.async.commit_group;" ::: "memory")
#define CP_WAIT(n)  asm volatile("cp.async.wait_group %0;" :: "n"(n) : "memory")

__device__ __forceinline__ uint32_t f2tf32(float v) {
    uint32_t r;
    asm("cvt.rna.tf32.f32 %0, %1;" : "=r"(r) : "f"(v));
    return r;
}

__device__ __forceinline__ void mma_tf32(float c[4], const uint32_t a[4],
                                         const uint32_t b[2]) {
    asm volatile(
        "mma.sync.aligned.m16n8k8.row.col.f32.tf32.tf32.f32 "
        "{%0,%1,%2,%3}, {%4,%5,%6,%7}, {%8,%9}, {%0,%1,%2,%3};"
        : "+f"(c[0]), "+f"(c[1]), "+f"(c[2]), "+f"(c[3])
        : "r"(a[0]), "r"(a[1]), "r"(a[2]), "r"(a[3]), "r"(b[0]), "r"(b[1]));
}

// ---------------------------------------------------------------------------
// tf32 warp-MMA GEMM:  D[m][n] = sum_k A[m][k] * B[n][k]  (+bias[n])
// CTA tile 128x128, K-tile 32, 8 warps (2x4), 64x32 per warp, m16n8k8 frags.
// Double-buffered cp.async.  z -> (b = z/NH, h = z%NH) with per-h/b strides.
// mode bit0: causal block skip (bx > by -> exit)
// mode bit1: K limited to (by+1)*128 (causal PV)
// ---------------------------------------------------------------------------
#define ASTR 36                     // padded floats per smem row
#define TILE_F (128 * ASTR)         // floats per 128x32 tile (padded)

__global__ __launch_bounds__(256) void gemm_mma(
    const float* __restrict__ A, long long lda, long long sAh, long long sAb,
    const float* __restrict__ B, long long ldb, long long sBh, long long sBb,
    float* __restrict__ C, long long ldc, long long sCh, long long sCb,
    int K, const float* __restrict__ bias, int mode)
{
    const int bx = blockIdx.x, by = blockIdx.y, bz = blockIdx.z;
    if ((mode & 1) && bx > by) return;

    int NT = K >> 5;
    if (mode & 2) { int lim = (by + 1) * 4; if (lim < NT) NT = lim; }

    const int zb = bz / NH, zh = bz % NH;
    const float* Ab = A + (long long)zh * sAh + (long long)zb * sAb
                        + (long long)(by * 128) * lda;
    const float* Bb = B + (long long)zh * sBh + (long long)zb * sBb
                        + (long long)(bx * 128) * ldb;
    float* Cb = C + (long long)zh * sCh + (long long)zb * sCb;

    extern __shared__ float sm[];   // [2 stages][A(128x36) | B(128x36)]

    const int tid  = threadIdx.x;
    const int wid  = tid >> 5;
    const int lane = tid & 31;
    const int g    = lane >> 2;      // 0..7
    const int tq   = lane & 3;       // 0..3
    const int wr   = (wid >> 2) * 64;   // warp row origin
    const int wc   = (wid & 3) * 32;    // warp col origin

    // accumulators: 4 m-tiles x 4 n-tiles x 4 frag floats
    float acc[4][4][4];
    #pragma unroll
    for (int i = 0; i < 4; i++)
        #pragma unroll
        for (int j = 0; j < 4; j++)
            #pragma unroll
            for (int f = 0; f < 4; f++) acc[i][j][f] = 0.f;

    // per-thread load slots: 4 float4 for A + 4 for B per tile
    int lrow[4], lcol[4];
    #pragma unroll
    for (int l = 0; l < 4; l++) {
        int ci = tid + l * 256;      // 0..1023
        lrow[l] = ci >> 3;           // 128 rows, 8 chunks each
        lcol[l] = (ci & 7) * 4;      // float offset
    }

    auto load_tile = [&](int t, int stage) {
        const int kt = t << 5;
        float* As = sm + stage * 2 * TILE_F;
        float* Bs = As + TILE_F;
        #pragma unroll
        for (int l = 0; l < 4; l++) {
            cp_async16(smem_u32(&As[lrow[l] * ASTR + lcol[l]]),
                       Ab + (long long)lrow[l] * lda + kt + lcol[l]);
            cp_async16(smem_u32(&Bs[lrow[l] * ASTR + lcol[l]]),
                       Bb + (long long)lrow[l] * ldb + kt + lcol[l]);
        }
    };

    // precomputed fragment row offsets
    int aOff[4], bOff[4];
    #pragma unroll
    for (int i = 0; i < 4; i++) aOff[i] = (wr + i * 16 + g) * ASTR;
    #pragma unroll
    for (int j = 0; j < 4; j++) bOff[j] = (wc + j * 8 + g) * ASTR;

    load_tile(0, 0);
    CP_COMMIT();

    for (int t = 0; t < NT; t++) {
        const int stage = t & 1;
        if (t + 1 < NT) {
            load_tile(t + 1, stage ^ 1);
            CP_COMMIT();
            CP_WAIT(1);
        } else {
            CP_WAIT(0);
        }
        __syncthreads();

        const float* As = sm + stage * 2 * TILE_F;
        const float* Bs = As + TILE_F;

        #pragma unroll
        for (int ks = 0; ks < 4; ks++) {
            const int k0 = ks * 8 + tq;
            uint32_t af[4][4], bf[4][2];
            #pragma unroll
            for (int i = 0; i < 4; i++) {
                af[i][0] = f2tf32(As[aOff[i] + k0]);
                af[i][1] = f2tf32(As[aOff[i] + 8 * ASTR + k0]);
                af[i][2] = f2tf32(As[aOff[i] + k0 + 4]);
                af[i][3] = f2tf32(As[aOff[i] + 8 * ASTR + k0 + 4]);
            }
            #pragma unroll
            for (int j = 0; j < 4; j++) {
                bf[j][0] = f2tf32(Bs[bOff[j] + k0]);
                bf[j][1] = f2tf32(Bs[bOff[j] + k0 + 4]);
            }
            #pragma unroll
            for (int i = 0; i < 4; i++)
                #pragma unroll
                for (int j = 0; j < 4; j++)
                    mma_tf32(acc[i][j], af[i], bf[j]);
        }
        __syncthreads();
    }

    // epilogue: frag (i,j): rows by*128+wr+i*16+g (+8), cols bx*128+wc+j*8+2*tq (+1)
    #pragma unroll
    for (int i = 0; i < 4; i++) {
        const int r0 = by * 128 + wr + i * 16 + g;
        #pragma unroll
        for (int j = 0; j < 4; j++) {
            const int c0 = bx * 128 + wc + j * 8 + 2 * tq;
            float v0 = acc[i][j][0], v1 = acc[i][j][1];
            float v2 = acc[i][j][2], v3 = acc[i][j][3];
            if (bias) {
                const float b0 = bias[c0], b1 = bias[c0 + 1];
                v0 += b0; v1 += b1; v2 += b0; v3 += b1;
            }
            float2 p0; p0.x = v0; p0.y = v1;
            float2 p1; p1.x = v2; p1.y = v3;
            *reinterpret_cast<float2*>(Cb + (long long)r0 * ldc + c0) = p0;
            *reinterpret_cast<float2*>(Cb + (long long)(r0 + 8) * ldc + c0) = p1;
        }
    }
}

// ---------------------------------------------------------------------------
// Transpose: out[c][r] = in[r][c]   (R, Cn multiples of 32)
// ---------------------------------------------------------------------------
__global__ void transpose_k(const float* __restrict__ in, float* __restrict__ out,
                            int R, int Cn)
{
    __shared__ float t[32][33];
    const int bx = blockIdx.x * 32, by = blockIdx.y * 32;
    const int tx = threadIdx.x, ty = threadIdx.y;
    #pragma unroll
    for (int yy = ty; yy < 32; yy += 8)
        t[yy][tx] = in[(size_t)(by + yy) * Cn + bx + tx];
    __syncthreads();
    #pragma unroll
    for (int yy = ty; yy < 32; yy += 8)
        out[(size_t)(bx + yy) * R + by + tx] = t[tx][yy];
}

// ---------------------------------------------------------------------------
// Causal softmax over S rows (in place -> P), scale folded in,
// zero-fill masked region up to the 128-block boundary.
// grid = (T, B*H), block = 256
// ---------------------------------------------------------------------------
__global__ __launch_bounds__(256) void softmax_causal(float* __restrict__ S)
{
    const int t  = blockIdx.x;
    const int bh = blockIdx.y;
    float* row = S + (size_t)bh * TT * TT + (size_t)t * TT;
    const int n   = t + 1;
    const int end = ((t >> 7) + 1) << 7;
    const float scale = 0.08838834764831845f;   // 1/sqrt(128)

    __shared__ float red[256];
    const int tid = threadIdx.x;

    float v[8];
    float mx = -1e30f;
    #pragma unroll
    for (int k = 0; k < 8; k++) {
        const int i = tid + k * 256;
        v[k] = (i < n) ? row[i] : -1e38f;
        mx = fmaxf(mx, v[k]);
    }
    red[tid] = mx;
    __syncthreads();
    for (int s = 128; s > 0; s >>= 1) {
        if (tid < s) red[tid] = fmaxf(red[tid], red[tid + s]);
        __syncthreads();
    }
    const float m = red[0] * scale;
    __syncthreads();

    float sum = 0.f;
    #pragma unroll
    for (int k = 0; k < 8; k++) {
        const int i = tid + k * 256;
        if (i < n) {
            v[k] = __expf(v[k] * scale - m);
            sum += v[k];
        }
    }
    red[tid] = sum;
    __syncthreads();
    for (int s = 128; s > 0; s >>= 1) {
        if (tid < s) red[tid] += red[tid + s];
        __syncthreads();
    }
    const float inv = 1.0f / red[0];

    #pragma unroll
    for (int k = 0; k < 8; k++) {
        const int i = tid + k * 256;
        if (i < n) row[i] = v[k] * inv;
        else if (i < end) row[i] = 0.f;
    }
}

// ---------------------------------------------------------------------------
// Launch
// ---------------------------------------------------------------------------
extern "C" void kernel_launch(void* const* d_in, const int* in_sizes, int n_in,
                              void* d_out, int out_size)
{
    (void)in_sizes; (void)n_in; (void)out_size;
    const float* x  = (const float*)d_in[0];
    const float* Wq = (const float*)d_in[1];
    const float* Wc = (const float*)d_in[2];
    const float* Wk = (const float*)d_in[3];
    const float* Wv = (const float*)d_in[4];
    const float* Wo = (const float*)d_in[5];
    const float* bo = (const float*)d_in[6];
    float* out = (float*)d_out;

    float *q, *c, *k, *vt, *y, *s, *wqt, *wct, *wkt, *wvt, *wot;
    cudaGetSymbolAddress((void**)&q,  g_q);
    cudaGetSymbolAddress((void**)&c,  g_c);
    cudaGetSymbolAddress((void**)&k,  g_k);
    cudaGetSymbolAddress((void**)&vt, g_vt);
    cudaGetSymbolAddress((void**)&y,  g_y);
    cudaGetSymbolAddress((void**)&s,  g_s);
    cudaGetSymbolAddress((void**)&wqt, g_wqt);
    cudaGetSymbolAddress((void**)&wct, g_wct);
    cudaGetSymbolAddress((void**)&wkt, g_wkt);
    cudaGetSymbolAddress((void**)&wvt, g_wvt);
    cudaGetSymbolAddress((void**)&wot, g_wot);

    const int gemm_smem = 2 * 2 * TILE_F * (int)sizeof(float);   // 73728 B
    cudaFuncSetAttribute(gemm_mma,
                         cudaFuncAttributeMaxDynamicSharedMemorySize, gemm_smem);

    dim3 tb(32, 8);
    transpose_k<<<dim3(CC / 32, CC / 32), tb>>>(Wq, wqt, CC, CC);
    transpose_k<<<dim3(DL / 32, CC / 32), tb>>>(Wc, wct, CC, DL);
    transpose_k<<<dim3(CC / 32, DL / 32), tb>>>(Wk, wkt, DL, CC);
    transpose_k<<<dim3(CC / 32, DL / 32), tb>>>(Wv, wvt, DL, CC);
    transpose_k<<<dim3(CC / 32, CC / 32), tb>>>(Wo, wot, CC, CC);

    dim3 blk(256);

    // q = x @ Wq
    gemm_mma<<<dim3(CC / 128, BT / 128, 1), blk, gemm_smem>>>(
        x, CC, 0, 0, wqt, CC, 0, 0, q, CC, 0, 0, CC, nullptr, 0);
    // c = x @ Wc
    gemm_mma<<<dim3(DL / 128, BT / 128, 1), blk, gemm_smem>>>(
        x, CC, 0, 0, wct, CC, 0, 0, c, DL, 0, 0, CC, nullptr, 0);
    // k = c @ Wk
    gemm_mma<<<dim3(CC / 128, BT / 128, 1), blk, gemm_smem>>>(
        c, DL, 0, 0, wkt, DL, 0, 0, k, CC, 0, 0, DL, nullptr, 0);
    // vT = Wv^T . c^T  -> vt[CC, BT]
    gemm_mma<<<dim3(BT / 128, CC / 128, 1), blk, gemm_smem>>>(
        wvt, DL, 0, 0, c, DL, 0, 0, vt, BT, 0, 0, DL, nullptr, 0);

    // S = Q_h . K_h^T per (b,h)   [causal block skip]
    gemm_mma<<<dim3(TT / 128, TT / 128, BHN), blk, gemm_smem>>>(
        q, CC, HSD, (long long)TT * CC,
        k, CC, HSD, (long long)TT * CC,
        s, TT, (long long)TT * TT, (long long)NH * TT * TT,
        HSD, nullptr, 1);

    // softmax (in place)
    softmax_causal<<<dim3(TT, BHN), blk>>>(s);

    // O = P . V^T   [causal K limit]
    gemm_mma<<<dim3(HSD / 128, TT / 128, BHN), blk, gemm_smem>>>(
        s, TT, (long long)TT * TT, (long long)NH * TT * TT,
        vt, BT, (long long)HSD * BT, TT,
        y, CC, HSD, (long long)TT * CC,
        TT, nullptr, 2);

    // out = y @ Wo + bo
    gemm_mma<<<dim3(CC / 128, BT / 128, 1), blk, gemm_smem>>>(
        y, CC, 0, 0, wot, CC, 0, 0, out, CC, 0, 0, CC, bo, 0);
}

// round 8
// speedup vs baseline: 3.2165x; 1.0357x over previous
#include <cuda_runtime.h>
#include <cstdint>

// ---------------------------------------------------------------------------
// Problem constants
// ---------------------------------------------------------------------------
#define BB 2
#define TT 2048
#define CC 2048
#define NH 16
#define HSD 128
#define DL 1024
#define BT (BB * TT)      // 4096
#define BHN (BB * NH)     // 32

// ---------------------------------------------------------------------------
// Scratch (__device__ globals; no cudaMalloc allowed)
// ---------------------------------------------------------------------------
__device__ float g_xr[BT * CC];         // tf32-rounded copy of x
__device__ float g_q[BT * CC];
__device__ float g_c[BT * DL];
__device__ float g_k[BT * CC];
__device__ float g_vt[CC * BT];         // v transposed: [C][B*T]
__device__ float g_y[BT * CC];
__device__ float g_s[134217728];        // 512MB scores: [BH][T][T]
__device__ float g_wqt[CC * CC];
__device__ float g_wct[DL * CC];
__device__ float g_wkt[CC * DL];
__device__ float g_wvt[CC * DL];
__device__ float g_wot[CC * CC];

// ---------------------------------------------------------------------------
// Helpers (portable PTX only: cp.async + mma.sync tf32, all sm_80+)
// ---------------------------------------------------------------------------
__device__ __forceinline__ uint32_t smem_u32(const void* p) {
    uint32_t a;
    asm("{ .reg .u64 t; cvta.to.shared.u64 t, %1; cvt.u32.u64 %0, t; }"
        : "=r"(a) : "l"(p));
    return a;
}

__device__ __forceinline__ void cp_async16(uint32_t dst, const void* src) {
    asm volatile("cp.async.cg.shared.global [%0], [%1], 16;"
                 :: "r"(dst), "l"(src));
}
#define CP_COMMIT() asm volatile("cp.async.commit_group;" ::: "memory")
#define CP_WAIT(n)  asm volatile("cp.async.wait_group %0;" :: "n"(n) : "memory")

__device__ __forceinline__ float rtf32(float v) {
    uint32_t r;
    asm("cvt.rna.tf32.f32 %0, %1;" : "=r"(r) : "f"(v));
    return __uint_as_float(r);
}

__device__ __forceinline__ void mma_tf32(float c[4], const uint32_t a[4],
                                         const uint32_t b[2]) {
    asm volatile(
        "mma.sync.aligned.m16n8k8.row.col.f32.tf32.tf32.f32 "
        "{%0,%1,%2,%3}, {%4,%5,%6,%7}, {%8,%9}, {%0,%1,%2,%3};"
        : "+f"(c[0]), "+f"(c[1]), "+f"(c[2]), "+f"(c[3])
        : "r"(a[0]), "r"(a[1]), "r"(a[2]), "r"(a[3]), "r"(b[0]), "r"(b[1]));
}

// ---------------------------------------------------------------------------
// tf32 warp-MMA GEMM:  D[m][n] = sum_k A[m][k] * B[n][k]  (+bias[n])
// Operands MUST already be tf32-rounded (loaded as raw bits, no cvt).
// CTA tile 128x128, K-tile 32, 8 warps (2x4), 64x32 per warp, m16n8k8 frags.
// Double-buffered cp.async.  z -> (b = z/NH, h = z%NH) with per-h/b strides.
// mode bit0: causal block skip (bx > by -> exit)
// mode bit1: K limited to (by+1)*128 (causal PV)
// mode bit2: round output to tf32 (it will be consumed as an MMA operand)
// ---------------------------------------------------------------------------
#define ASTR 36                     // padded floats per smem row
#define TILE_F (128 * ASTR)         // floats per 128x32 tile (padded)

__global__ __launch_bounds__(256) void gemm_mma(
    const float* __restrict__ A, long long lda, long long sAh, long long sAb,
    const float* __restrict__ B, long long ldb, long long sBh, long long sBb,
    float* __restrict__ C, long long ldc, long long sCh, long long sCb,
    int K, const float* __restrict__ bias, int mode)
{
    const int bx = blockIdx.x, by = blockIdx.y, bz = blockIdx.z;
    if ((mode & 1) && bx > by) return;

    int NT = K >> 5;
    if (mode & 2) { int lim = (by + 1) * 4; if (lim < NT) NT = lim; }

    const int zb = bz / NH, zh = bz % NH;
    const float* Ab = A + (long long)zh * sAh + (long long)zb * sAb
                        + (long long)(by * 128) * lda;
    const float* Bb = B + (long long)zh * sBh + (long long)zb * sBb
                        + (long long)(bx * 128) * ldb;
    float* Cb = C + (long long)zh * sCh + (long long)zb * sCb;

    extern __shared__ float sm[];   // [2 stages][A(128x36) | B(128x36)]

    const int tid  = threadIdx.x;
    const int wid  = tid >> 5;
    const int lane = tid & 31;
    const int g    = lane >> 2;      // 0..7
    const int tq   = lane & 3;       // 0..3
    const int wr   = (wid >> 2) * 64;   // warp row origin
    const int wc   = (wid & 3) * 32;    // warp col origin

    float acc[4][4][4];
    #pragma unroll
    for (int i = 0; i < 4; i++)
        #pragma unroll
        for (int j = 0; j < 4; j++)
            #pragma unroll
            for (int f = 0; f < 4; f++) acc[i][j][f] = 0.f;

    int lrow[4], lcol[4];
    #pragma unroll
    for (int l = 0; l < 4; l++) {
        int ci = tid + l * 256;      // 0..1023
        lrow[l] = ci >> 3;           // 128 rows, 8 chunks each
        lcol[l] = (ci & 7) * 4;      // float offset
    }

    auto load_tile = [&](int t, int stage) {
        const int kt = t << 5;
        float* As = sm + stage * 2 * TILE_F;
        float* Bs = As + TILE_F;
        #pragma unroll
        for (int l = 0; l < 4; l++) {
            cp_async16(smem_u32(&As[lrow[l] * ASTR + lcol[l]]),
                       Ab + (long long)lrow[l] * lda + kt + lcol[l]);
            cp_async16(smem_u32(&Bs[lrow[l] * ASTR + lcol[l]]),
                       Bb + (long long)lrow[l] * ldb + kt + lcol[l]);
        }
    };

    int aOff[4], bOff[4];
    #pragma unroll
    for (int i = 0; i < 4; i++) aOff[i] = (wr + i * 16 + g) * ASTR;
    #pragma unroll
    for (int j = 0; j < 4; j++) bOff[j] = (wc + j * 8 + g) * ASTR;

    load_tile(0, 0);
    CP_COMMIT();

    for (int t = 0; t < NT; t++) {
        const int stage = t & 1;
        if (t + 1 < NT) {
            load_tile(t + 1, stage ^ 1);
            CP_COMMIT();
            CP_WAIT(1);
        } else {
            CP_WAIT(0);
        }
        __syncthreads();

        const uint32_t* As = reinterpret_cast<const uint32_t*>(
            sm + stage * 2 * TILE_F);
        const uint32_t* Bs = As + TILE_F;

        #pragma unroll
        for (int ks = 0; ks < 4; ks++) {
            const int k0 = ks * 8 + tq;
            uint32_t af[4][4], bf[4][2];
            #pragma unroll
            for (int i = 0; i < 4; i++) {
                af[i][0] = As[aOff[i] + k0];
                af[i][1] = As[aOff[i] + 8 * ASTR + k0];
                af[i][2] = As[aOff[i] + k0 + 4];
                af[i][3] = As[aOff[i] + 8 * ASTR + k0 + 4];
            }
            #pragma unroll
            for (int j = 0; j < 4; j++) {
                bf[j][0] = Bs[bOff[j] + k0];
                bf[j][1] = Bs[bOff[j] + k0 + 4];
            }
            #pragma unroll
            for (int i = 0; i < 4; i++)
                #pragma unroll
                for (int j = 0; j < 4; j++)
                    mma_tf32(acc[i][j], af[i], bf[j]);
        }
        __syncthreads();
    }

    const bool rnd = (mode & 4) != 0;
    #pragma unroll
    for (int i = 0; i < 4; i++) {
        const int r0 = by * 128 + wr + i * 16 + g;
        #pragma unroll
        for (int j = 0; j < 4; j++) {
            const int c0 = bx * 128 + wc + j * 8 + 2 * tq;
            float v0 = acc[i][j][0], v1 = acc[i][j][1];
            float v2 = acc[i][j][2], v3 = acc[i][j][3];
            if (bias) {
                const float b0 = bias[c0], b1 = bias[c0 + 1];
                v0 += b0; v1 += b1; v2 += b0; v3 += b1;
            }
            if (rnd) {
                v0 = rtf32(v0); v1 = rtf32(v1);
                v2 = rtf32(v2); v3 = rtf32(v3);
            }
            float2 p0; p0.x = v0; p0.y = v1;
            float2 p1; p1.x = v2; p1.y = v3;
            *reinterpret_cast<float2*>(Cb + (long long)r0 * ldc + c0) = p0;
            *reinterpret_cast<float2*>(Cb + (long long)(r0 + 8) * ldc + c0) = p1;
        }
    }
}

// ---------------------------------------------------------------------------
// Transpose + scale + tf32-round: out[c][r] = round(in[r][c] * mul)
// ---------------------------------------------------------------------------
__global__ void transpose_k(const float* __restrict__ in, float* __restrict__ out,
                            int R, int Cn, float mul)
{
    __shared__ float t[32][33];
    const int bx = blockIdx.x * 32, by = blockIdx.y * 32;
    const int tx = threadIdx.x, ty = threadIdx.y;
    #pragma unroll
    for (int yy = ty; yy < 32; yy += 8)
        t[yy][tx] = rtf32(in[(size_t)(by + yy) * Cn + bx + tx] * mul);
    __syncthreads();
    #pragma unroll
    for (int yy = ty; yy < 32; yy += 8)
        out[(size_t)(bx + yy) * R + by + tx] = t[tx][yy];
}

// ---------------------------------------------------------------------------
// Elementwise tf32-round copy (x -> xr), float4 vectorized
// ---------------------------------------------------------------------------
__global__ void round_copy(const float4* __restrict__ in, float4* __restrict__ out,
                           int n4)
{
    int i = blockIdx.x * blockDim.x + threadIdx.x;
    if (i < n4) {
        float4 v = in[i];
        v.x = rtf32(v.x); v.y = rtf32(v.y);
        v.z = rtf32(v.z); v.w = rtf32(v.w);
        out[i] = v;
    }
}

// ---------------------------------------------------------------------------
// Causal softmax over S rows (in place -> P, tf32-rounded), scale already
// folded into Wq. Zero-fill masked region up to the 128-block boundary.
// grid = (T, B*H), block = 256
// ---------------------------------------------------------------------------
__global__ __launch_bounds__(256) void softmax_causal(float* __restrict__ S)
{
    const int t  = blockIdx.x;
    const int bh = blockIdx.y;
    float* row = S + (size_t)bh * TT * TT + (size_t)t * TT;
    const int n   = t + 1;
    const int end = ((t >> 7) + 1) << 7;

    __shared__ float red[256];
    const int tid = threadIdx.x;

    float v[8];
    float mx = -1e30f;
    #pragma unroll
    for (int k = 0; k < 8; k++) {
        const int i = tid + k * 256;
        v[k] = (i < n) ? row[i] : -1e38f;
        mx = fmaxf(mx, v[k]);
    }
    red[tid] = mx;
    __syncthreads();
    for (int s = 128; s > 0; s >>= 1) {
        if (tid < s) red[tid] = fmaxf(red[tid], red[tid + s]);
        __syncthreads();
    }
    const float m = red[0];
    __syncthreads();

    float sum = 0.f;
    #pragma unroll
    for (int k = 0; k < 8; k++) {
        const int i = tid + k * 256;
        if (i < n) {
            v[k] = __expf(v[k] - m);
            sum += v[k];
        }
    }
    red[tid] = sum;
    __syncthreads();
    for (int s = 128; s > 0; s >>= 1) {
        if (tid < s) red[tid] += red[tid + s];
        __syncthreads();
    }
    const float inv = 1.0f / red[0];

    #pragma unroll
    for (int k = 0; k < 8; k++) {
        const int i = tid + k * 256;
        if (i < n) row[i] = rtf32(v[k] * inv);
        else if (i < end) row[i] = 0.f;
    }
}

// ---------------------------------------------------------------------------
// Launch
// ---------------------------------------------------------------------------
extern "C" void kernel_launch(void* const* d_in, const int* in_sizes, int n_in,
                              void* d_out, int out_size)
{
    (void)in_sizes; (void)n_in; (void)out_size;
    const float* x  = (const float*)d_in[0];
    const float* Wq = (const float*)d_in[1];
    const float* Wc = (const float*)d_in[2];
    const float* Wk = (const float*)d_in[3];
    const float* Wv = (const float*)d_in[4];
    const float* Wo = (const float*)d_in[5];
    const float* bo = (const float*)d_in[6];
    float* out = (float*)d_out;

    float *xr, *q, *c, *k, *vt, *y, *s, *wqt, *wct, *wkt, *wvt, *wot;
    cudaGetSymbolAddress((void**)&xr, g_xr);
    cudaGetSymbolAddress((void**)&q,  g_q);
    cudaGetSymbolAddress((void**)&c,  g_c);
    cudaGetSymbolAddress((void**)&k,  g_k);
    cudaGetSymbolAddress((void**)&vt, g_vt);
    cudaGetSymbolAddress((void**)&y,  g_y);
    cudaGetSymbolAddress((void**)&s,  g_s);
    cudaGetSymbolAddress((void**)&wqt, g_wqt);
    cudaGetSymbolAddress((void**)&wct, g_wct);
    cudaGetSymbolAddress((void**)&wkt, g_wkt);
    cudaGetSymbolAddress((void**)&wvt, g_wvt);
    cudaGetSymbolAddress((void**)&wot, g_wot);

    const int gemm_smem = 2 * 2 * TILE_F * (int)sizeof(float);   // 73728 B
    cudaFuncSetAttribute(gemm_mma,
                         cudaFuncAttributeMaxDynamicSharedMemorySize, gemm_smem);

    const float scale = 0.08838834764831845f;   // 1/sqrt(128), folded into WqT

    dim3 tb(32, 8);
    transpose_k<<<dim3(CC / 32, CC / 32), tb>>>(Wq, wqt, CC, CC, scale);
    transpose_k<<<dim3(DL / 32, CC / 32), tb>>>(Wc, wct, CC, DL, 1.f);
    transpose_k<<<dim3(CC / 32, DL / 32), tb>>>(Wk, wkt, DL, CC, 1.f);
    transpose_k<<<dim3(CC / 32, DL / 32), tb>>>(Wv, wvt, DL, CC, 1.f);
    transpose_k<<<dim3(CC / 32, CC / 32), tb>>>(Wo, wot, CC, CC, 1.f);

    round_copy<<<(BT * CC / 4 + 255) / 256, 256>>>(
        (const float4*)x, (float4*)xr, BT * CC / 4);

    dim3 blk(256);

    // q = xr @ Wq' (scale folded), rounded
    gemm_mma<<<dim3(CC / 128, BT / 128, 1), blk, gemm_smem>>>(
        xr, CC, 0, 0, wqt, CC, 0, 0, q, CC, 0, 0, CC, nullptr, 4);
    // c = xr @ Wc, rounded
    gemm_mma<<<dim3(DL / 128, BT / 128, 1), blk, gemm_smem>>>(
        xr, CC, 0, 0, wct, CC, 0, 0, c, DL, 0, 0, CC, nullptr, 4);
    // k = c @ Wk, rounded
    gemm_mma<<<dim3(CC / 128, BT / 128, 1), blk, gemm_smem>>>(
        c, DL, 0, 0, wkt, DL, 0, 0, k, CC, 0, 0, DL, nullptr, 4);
    // vT = Wv^T . c^T -> vt[CC, BT], rounded
    gemm_mma<<<dim3(BT / 128, CC / 128, 1), blk, gemm_smem>>>(
        wvt, DL, 0, 0, c, DL, 0, 0, vt, BT, 0, 0, DL, nullptr, 4);

    // S = Q_h . K_h^T per (b,h)   [causal block skip], NOT rounded
    gemm_mma<<<dim3(TT / 128, TT / 128, BHN), blk, gemm_smem>>>(
        q, CC, HSD, (long long)TT * CC,
        k, CC, HSD, (long long)TT * CC,
        s, TT, (long long)TT * TT, (long long)NH * TT * TT,
        HSD, nullptr, 1);

    // softmax (in place, writes rounded P)
    softmax_causal<<<dim3(TT, BHN), blk>>>(s);

    // O = P . V^T   [causal K limit], rounded (consumed by out GEMM)
    gemm_mma<<<dim3(HSD / 128, TT / 128, BHN), blk, gemm_smem>>>(
        s, TT, (long long)TT * TT, (long long)NH * TT * TT,
        vt, BT, (long long)HSD * BT, TT,
        y, CC, HSD, (long long)TT * CC,
        TT, nullptr, 6);

    // out = y @ Wo + bo   (full fp32 epilogue)
    gemm_mma<<<dim3(CC / 128, BT / 128, 1), blk, gemm_smem>>>(
        y, CC, 0, 0, wot, CC, 0, 0, out, CC, 0, 0, CC, bo, 0);
}

// round 9
// speedup vs baseline: 3.3712x; 1.0481x over previous
#include <cuda_runtime.h>
#include <cstdint>

// ---------------------------------------------------------------------------
// Problem constants
// ---------------------------------------------------------------------------
#define BB 2
#define TT 2048
#define CC 2048
#define NH 16
#define HSD 128
#define DL 1024
#define BT (BB * TT)      // 4096
#define BHN (BB * NH)     // 32

// ---------------------------------------------------------------------------
// Scratch (__device__ globals; no cudaMalloc allowed)
// ---------------------------------------------------------------------------
__device__ float g_xr[BT * CC];         // tf32-rounded copy of x
__device__ float g_q[BT * CC];
__device__ float g_c[BT * DL];
__device__ float g_k[BT * CC];
__device__ float g_vt[CC * BT];         // v transposed: [C][B*T]
__device__ float g_y[BT * CC];
__device__ float g_s[134217728];        // 512MB scores: [BH][T][T]
__device__ float g_wqt[CC * CC];
__device__ float g_wct[DL * CC];
__device__ float g_wkt[CC * DL];
__device__ float g_wvt[CC * DL];
__device__ float g_wot[CC * CC];

// ---------------------------------------------------------------------------
// Helpers (portable PTX only: cp.async + mma.sync tf32, all sm_80+)
// ---------------------------------------------------------------------------
__device__ __forceinline__ uint32_t smem_u32(const void* p) {
    uint32_t a;
    asm("{ .reg .u64 t; cvta.to.shared.u64 t, %1; cvt.u32.u64 %0, t; }"
        : "=r"(a) : "l"(p));
    return a;
}

__device__ __forceinline__ void cp_async16(uint32_t dst, const void* src) {
    asm volatile("cp.async.cg.shared.global [%0], [%1], 16;"
                 :: "r"(dst), "l"(src));
}
#define CP_COMMIT() asm volatile("cp.async.commit_group;" ::: "memory")
#define CP_WAIT(n)  asm volatile("cp.async.wait_group %0;" :: "n"(n) : "memory")

__device__ __forceinline__ float rtf32(float v) {
    uint32_t r;
    asm("cvt.rna.tf32.f32 %0, %1;" : "=r"(r) : "f"(v));
    return __uint_as_float(r);
}

__device__ __forceinline__ void mma_tf32(float c[4], const uint32_t a[4],
                                         const uint32_t b[2]) {
    asm volatile(
        "mma.sync.aligned.m16n8k8.row.col.f32.tf32.tf32.f32 "
        "{%0,%1,%2,%3}, {%4,%5,%6,%7}, {%8,%9}, {%0,%1,%2,%3};"
        : "+f"(c[0]), "+f"(c[1]), "+f"(c[2]), "+f"(c[3])
        : "r"(a[0]), "r"(a[1]), "r"(a[2]), "r"(a[3]), "r"(b[0]), "r"(b[1]));
}

// ---------------------------------------------------------------------------
// tf32 warp-MMA GEMM:  D[m][n] = sum_k A[m][k] * B[n][k]  (+bias[n])
// Operands MUST already be tf32-rounded (loaded as raw bits, no cvt).
// CTA tile 128x128, K-tile 32, 8 warps (2x4), 64x32 per warp, m16n8k8 frags.
// Double-buffered cp.async, 2 CTAs/SM (128-reg cap).
// mode bit0: causal block skip (bx > by -> exit)
// mode bit1: K limited to (by+1)*128 (causal PV)
// mode bit2: round output to tf32 (it will be consumed as an MMA operand)
// ---------------------------------------------------------------------------
#define ASTR 36                     // padded floats per smem row
#define TILE_F (128 * ASTR)         // floats per 128x32 tile (padded)

__global__ __launch_bounds__(256, 2) void gemm_mma(
    const float* __restrict__ A, long long lda, long long sAh, long long sAb,
    const float* __restrict__ B, long long ldb, long long sBh, long long sBb,
    float* __restrict__ C, long long ldc, long long sCh, long long sCb,
    int K, const float* __restrict__ bias, int mode)
{
    const int bx = blockIdx.x, by = blockIdx.y, bz = blockIdx.z;
    if ((mode & 1) && bx > by) return;

    int NT = K >> 5;
    if (mode & 2) { int lim = (by + 1) * 4; if (lim < NT) NT = lim; }

    const int zb = bz / NH, zh = bz % NH;
    const float* Ab = A + (long long)zh * sAh + (long long)zb * sAb
                        + (long long)(by * 128) * lda;
    const float* Bb = B + (long long)zh * sBh + (long long)zb * sBb
                        + (long long)(bx * 128) * ldb;
    float* Cb = C + (long long)zh * sCh + (long long)zb * sCb;

    extern __shared__ float sm[];   // [2 stages][A(128x36) | B(128x36)]

    const int tid  = threadIdx.x;
    const int wid  = tid >> 5;
    const int lane = tid & 31;
    const int g    = lane >> 2;      // 0..7
    const int tq   = lane & 3;       // 0..3
    const int wr   = (wid >> 2) * 64;   // warp row origin
    const int wc   = (wid & 3) * 32;    // warp col origin

    float acc[4][4][4];
    #pragma unroll
    for (int i = 0; i < 4; i++)
        #pragma unroll
        for (int j = 0; j < 4; j++)
            #pragma unroll
            for (int f = 0; f < 4; f++) acc[i][j][f] = 0.f;

    const int lrow = tid >> 3;           // base row (128 rows, 8 chunks each)
    const int lcol = (tid & 7) * 4;      // float offset

    auto load_tile = [&](int t, int stage) {
        const int kt = t << 5;
        float* As = sm + stage * 2 * TILE_F;
        float* Bs = As + TILE_F;
        #pragma unroll
        for (int l = 0; l < 4; l++) {
            const int r = lrow + l * 32;
            cp_async16(smem_u32(&As[r * ASTR + lcol]),
                       Ab + (long long)r * lda + kt + lcol);
            cp_async16(smem_u32(&Bs[r * ASTR + lcol]),
                       Bb + (long long)r * ldb + kt + lcol);
        }
    };

    int aOff[4], bOff[4];
    #pragma unroll
    for (int i = 0; i < 4; i++) aOff[i] = (wr + i * 16 + g) * ASTR;
    #pragma unroll
    for (int j = 0; j < 4; j++) bOff[j] = (wc + j * 8 + g) * ASTR;

    load_tile(0, 0);
    CP_COMMIT();

    for (int t = 0; t < NT; t++) {
        const int stage = t & 1;
        if (t + 1 < NT) {
            load_tile(t + 1, stage ^ 1);
            CP_COMMIT();
            CP_WAIT(1);
        } else {
            CP_WAIT(0);
        }
        __syncthreads();

        const uint32_t* As = reinterpret_cast<const uint32_t*>(
            sm + stage * 2 * TILE_F);
        const uint32_t* Bs = As + TILE_F;

        #pragma unroll
        for (int ks = 0; ks < 4; ks++) {
            const int k0 = ks * 8 + tq;
            uint32_t af[4][4], bf[4][2];
            #pragma unroll
            for (int i = 0; i < 4; i++) {
                af[i][0] = As[aOff[i] + k0];
                af[i][1] = As[aOff[i] + 8 * ASTR + k0];
                af[i][2] = As[aOff[i] + k0 + 4];
                af[i][3] = As[aOff[i] + 8 * ASTR + k0 + 4];
            }
            #pragma unroll
            for (int j = 0; j < 4; j++) {
                bf[j][0] = Bs[bOff[j] + k0];
                bf[j][1] = Bs[bOff[j] + k0 + 4];
            }
            #pragma unroll
            for (int i = 0; i < 4; i++)
                #pragma unroll
                for (int j = 0; j < 4; j++)
                    mma_tf32(acc[i][j], af[i], bf[j]);
        }
        __syncthreads();
    }

    const bool rnd = (mode & 4) != 0;
    #pragma unroll
    for (int i = 0; i < 4; i++) {
        const int r0 = by * 128 + wr + i * 16 + g;
        #pragma unroll
        for (int j = 0; j < 4; j++) {
            const int c0 = bx * 128 + wc + j * 8 + 2 * tq;
            float v0 = acc[i][j][0], v1 = acc[i][j][1];
            float v2 = acc[i][j][2], v3 = acc[i][j][3];
            if (bias) {
                const float b0 = bias[c0], b1 = bias[c0 + 1];
                v0 += b0; v1 += b1; v2 += b0; v3 += b1;
            }
            if (rnd) {
                v0 = rtf32(v0); v1 = rtf32(v1);
                v2 = rtf32(v2); v3 = rtf32(v3);
            }
            float2 p0; p0.x = v0; p0.y = v1;
            float2 p1; p1.x = v2; p1.y = v3;
            *reinterpret_cast<float2*>(Cb + (long long)r0 * ldc + c0) = p0;
            *reinterpret_cast<float2*>(Cb + (long long)(r0 + 8) * ldc + c0) = p1;
        }
    }
}

// ---------------------------------------------------------------------------
// Transpose + scale + tf32-round: out[c][r] = round(in[r][c] * mul)
// ---------------------------------------------------------------------------
__global__ void transpose_k(const float* __restrict__ in, float* __restrict__ out,
                            int R, int Cn, float mul)
{
    __shared__ float t[32][33];
    const int bx = blockIdx.x * 32, by = blockIdx.y * 32;
    const int tx = threadIdx.x, ty = threadIdx.y;
    #pragma unroll
    for (int yy = ty; yy < 32; yy += 8)
        t[yy][tx] = rtf32(in[(size_t)(by + yy) * Cn + bx + tx] * mul);
    __syncthreads();
    #pragma unroll
    for (int yy = ty; yy < 32; yy += 8)
        out[(size_t)(bx + yy) * R + by + tx] = t[tx][yy];
}

// ---------------------------------------------------------------------------
// Elementwise tf32-round copy (x -> xr), float4 vectorized
// ---------------------------------------------------------------------------
__global__ void round_copy(const float4* __restrict__ in, float4* __restrict__ out,
                           int n4)
{
    int i = blockIdx.x * blockDim.x + threadIdx.x;
    if (i < n4) {
        float4 v = in[i];
        v.x = rtf32(v.x); v.y = rtf32(v.y);
        v.z = rtf32(v.z); v.w = rtf32(v.w);
        out[i] = v;
    }
}

// ---------------------------------------------------------------------------
// Causal softmax over S rows (in place -> P, tf32-rounded), scale already
// folded into Wq. Zero-fill masked region up to the 128-block boundary.
// grid = (T, B*H), block = 256.  float4 loads (rows are 16B aligned).
// ---------------------------------------------------------------------------
__global__ __launch_bounds__(256) void softmax_causal(float* __restrict__ S)
{
    const int t  = blockIdx.x;
    const int bh = blockIdx.y;
    float* row = S + (size_t)bh * TT * TT + (size_t)t * TT;
    const int n   = t + 1;
    const int end = ((t >> 7) + 1) << 7;

    __shared__ float red[256];
    const int tid = threadIdx.x;

    // 2 float4 per thread covers 2048 columns
    float4 v[2];
    float mx = -1e30f;
    #pragma unroll
    for (int k = 0; k < 2; k++) {
        const int i = (tid + k * 256) * 4;
        float4 val = *reinterpret_cast<const float4*>(row + i);
        val.x = (i + 0 < n) ? val.x : -1e38f;
        val.y = (i + 1 < n) ? val.y : -1e38f;
        val.z = (i + 2 < n) ? val.z : -1e38f;
        val.w = (i + 3 < n) ? val.w : -1e38f;
        v[k] = val;
        mx = fmaxf(mx, fmaxf(fmaxf(val.x, val.y), fmaxf(val.z, val.w)));
    }
    red[tid] = mx;
    __syncthreads();
    for (int s = 128; s > 0; s >>= 1) {
        if (tid < s) red[tid] = fmaxf(red[tid], red[tid + s]);
        __syncthreads();
    }
    const float m = red[0];
    __syncthreads();

    float sum = 0.f;
    #pragma unroll
    for (int k = 0; k < 2; k++) {
        float4 e;
        e.x = __expf(v[k].x - m);
        e.y = __expf(v[k].y - m);
        e.z = __expf(v[k].z - m);
        e.w = __expf(v[k].w - m);
        v[k] = e;
        sum += e.x + e.y + e.z + e.w;   // exp(-1e38) == 0, safe to include
    }
    red[tid] = sum;
    __syncthreads();
    for (int s = 128; s > 0; s >>= 1) {
        if (tid < s) red[tid] += red[tid + s];
        __syncthreads();
    }
    const float inv = 1.0f / red[0];

    #pragma unroll
    for (int k = 0; k < 2; k++) {
        const int i = (tid + k * 256) * 4;
        if (i < end) {
            float4 o;
            o.x = rtf32(v[k].x * inv);
            o.y = rtf32(v[k].y * inv);
            o.z = rtf32(v[k].z * inv);
            o.w = rtf32(v[k].w * inv);
            *reinterpret_cast<float4*>(row + i) = o;
        }
    }
}

// ---------------------------------------------------------------------------
// Launch
// ---------------------------------------------------------------------------
extern "C" void kernel_launch(void* const* d_in, const int* in_sizes, int n_in,
                              void* d_out, int out_size)
{
    (void)in_sizes; (void)n_in; (void)out_size;
    const float* x  = (const float*)d_in[0];
    const float* Wq = (const float*)d_in[1];
    const float* Wc = (const float*)d_in[2];
    const float* Wk = (const float*)d_in[3];
    const float* Wv = (const float*)d_in[4];
    const float* Wo = (const float*)d_in[5];
    const float* bo = (const float*)d_in[6];
    float* out = (float*)d_out;

    float *xr, *q, *c, *k, *vt, *y, *s, *wqt, *wct, *wkt, *wvt, *wot;
    cudaGetSymbolAddress((void**)&xr, g_xr);
    cudaGetSymbolAddress((void**)&q,  g_q);
    cudaGetSymbolAddress((void**)&c,  g_c);
    cudaGetSymbolAddress((void**)&k,  g_k);
    cudaGetSymbolAddress((void**)&vt, g_vt);
    cudaGetSymbolAddress((void**)&y,  g_y);
    cudaGetSymbolAddress((void**)&s,  g_s);
    cudaGetSymbolAddress((void**)&wqt, g_wqt);
    cudaGetSymbolAddress((void**)&wct, g_wct);
    cudaGetSymbolAddress((void**)&wkt, g_wkt);
    cudaGetSymbolAddress((void**)&wvt, g_wvt);
    cudaGetSymbolAddress((void**)&wot, g_wot);

    const int gemm_smem = 2 * 2 * TILE_F * (int)sizeof(float);   // 73728 B
    cudaFuncSetAttribute(gemm_mma,
                         cudaFuncAttributeMaxDynamicSharedMemorySize, gemm_smem);

    const float scale = 0.08838834764831845f;   // 1/sqrt(128), folded into WqT

    dim3 tb(32, 8);
    transpose_k<<<dim3(CC / 32, CC / 32), tb>>>(Wq, wqt, CC, CC, scale);
    transpose_k<<<dim3(DL / 32, CC / 32), tb>>>(Wc, wct, CC, DL, 1.f);
    transpose_k<<<dim3(CC / 32, DL / 32), tb>>>(Wk, wkt, DL, CC, 1.f);
    transpose_k<<<dim3(CC / 32, DL / 32), tb>>>(Wv, wvt, DL, CC, 1.f);
    transpose_k<<<dim3(CC / 32, CC / 32), tb>>>(Wo, wot, CC, CC, 1.f);

    round_copy<<<(BT * CC / 4 + 255) / 256, 256>>>(
        (const float4*)x, (float4*)xr, BT * CC / 4);

    dim3 blk(256);

    // q = xr @ Wq' (scale folded), rounded
    gemm_mma<<<dim3(CC / 128, BT / 128, 1), blk, gemm_smem>>>(
        xr, CC, 0, 0, wqt, CC, 0, 0, q, CC, 0, 0, CC, nullptr, 4);
    // c = xr @ Wc, rounded
    gemm_mma<<<dim3(DL / 128, BT / 128, 1), blk, gemm_smem>>>(
        xr, CC, 0, 0, wct, CC, 0, 0, c, DL, 0, 0, CC, nullptr, 4);
    // k = c @ Wk, rounded
    gemm_mma<<<dim3(CC / 128, BT / 128, 1), blk, gemm_smem>>>(
        c, DL, 0, 0, wkt, DL, 0, 0, k, CC, 0, 0, DL, nullptr, 4);
    // vT = Wv^T . c^T -> vt[CC, BT], rounded
    gemm_mma<<<dim3(BT / 128, CC / 128, 1), blk, gemm_smem>>>(
        wvt, DL, 0, 0, c, DL, 0, 0, vt, BT, 0, 0, DL, nullptr, 4);

    // S = Q_h . K_h^T per (b,h)   [causal block skip], NOT rounded
    gemm_mma<<<dim3(TT / 128, TT / 128, BHN), blk, gemm_smem>>>(
        q, CC, HSD, (long long)TT * CC,
        k, CC, HSD, (long long)TT * CC,
        s, TT, (long long)TT * TT, (long long)NH * TT * TT,
        HSD, nullptr, 1);

    // softmax (in place, writes rounded P)
    softmax_causal<<<dim3(TT, BHN), blk>>>(s);

    // O = P . V^T   [causal K limit], rounded (consumed by out GEMM)
    gemm_mma<<<dim3(HSD / 128, TT / 128, BHN), blk, gemm_smem>>>(
        s, TT, (long long)TT * TT, (long long)NH * TT * TT,
        vt, BT, (long long)HSD * BT, TT,
        y, CC, HSD, (long long)TT * CC,
        TT, nullptr, 6);

    // out = y @ Wo + bo   (full fp32 epilogue)
    gemm_mma<<<dim3(CC / 128, BT / 128, 1), blk, gemm_smem>>>(
        y, CC, 0, 0, wot, CC, 0, 0, out, CC, 0, 0, CC, bo, 0);
}

// round 10
// speedup vs baseline: 3.4278x; 1.0168x over previous
#include <cuda_runtime.h>
#include <cstdint>

// ---------------------------------------------------------------------------
// Problem constants
// ---------------------------------------------------------------------------
#define BB 2
#define TT 2048
#define CC 2048
#define NH 16
#define HSD 128
#define DL 1024
#define BT (BB * TT)      // 4096
#define BHN (BB * NH)     // 32

// ---------------------------------------------------------------------------
// Scratch (__device__ globals; no cudaMalloc allowed)
// ---------------------------------------------------------------------------
__device__ float g_xr[BT * CC];         // tf32-rounded copy of x
__device__ float g_q[BT * CC];
__device__ float g_c[BT * DL];
__device__ float g_k[BT * CC];
__device__ float g_vt[CC * BT];         // v transposed: [C][B*T]
__device__ float g_y[BT * CC];
__device__ float g_s[134217728];        // 512MB scores: [BH][T][T]
__device__ float g_wqt[CC * CC];
__device__ float g_wct[DL * CC];
__device__ float g_wkt[CC * DL];
__device__ float g_wvt[CC * DL];
__device__ float g_wot[CC * CC];

// ---------------------------------------------------------------------------
// Helpers (portable PTX only: cp.async + mma.sync tf32, all sm_80+)
// ---------------------------------------------------------------------------
__device__ __forceinline__ uint32_t smem_u32(const void* p) {
    uint32_t a;
    asm("{ .reg .u64 t; cvta.to.shared.u64 t, %1; cvt.u32.u64 %0, t; }"
        : "=r"(a) : "l"(p));
    return a;
}

__device__ __forceinline__ void cp_async16(uint32_t dst, const void* src) {
    asm volatile("cp.async.cg.shared.global [%0], [%1], 16;"
                 :: "r"(dst), "l"(src));
}
#define CP_COMMIT() asm volatile("cp.async.commit_group;" ::: "memory")
#define CP_WAIT(n)  asm volatile("cp.async.wait_group %0;" :: "n"(n) : "memory")

__device__ __forceinline__ float rtf32(float v) {
    uint32_t r;
    asm("cvt.rna.tf32.f32 %0, %1;" : "=r"(r) : "f"(v));
    return __uint_as_float(r);
}

__device__ __forceinline__ void mma_tf32(float c[4], const uint32_t a[4],
                                         const uint32_t b[2]) {
    asm volatile(
        "mma.sync.aligned.m16n8k8.row.col.f32.tf32.tf32.f32 "
        "{%0,%1,%2,%3}, {%4,%5,%6,%7}, {%8,%9}, {%0,%1,%2,%3};"
        : "+f"(c[0]), "+f"(c[1]), "+f"(c[2]), "+f"(c[3])
        : "r"(a[0]), "r"(a[1]), "r"(a[2]), "r"(a[3]), "r"(b[0]), "r"(b[1]));
}

// ---------------------------------------------------------------------------
// tf32 warp-MMA GEMM:  D[m][n] = sum_k A[m][k] * B[n][k]  (+bias[n])
// Operands MUST already be tf32-rounded (loaded as raw bits, no cvt).
// CTA tile 128x128, K-tile 32, 8 warps (2x4), 64x32 per warp, m16n8k8 frags.
// 3-stage cp.async ring, ONE __syncthreads per K-iteration, 2 CTAs/SM.
// mode bit0: causal block skip (bx > by -> exit)
// mode bit1: K limited to (by+1)*128 (causal PV)
// mode bit2: round output to tf32 (it will be consumed as an MMA operand)
// mode bit3: reverse by mapping (heavy causal blocks launch first)
// ---------------------------------------------------------------------------
#define ASTR 36                     // padded floats per smem row
#define TILE_F (128 * ASTR)         // floats per 128x32 tile (padded)
#define NSTAGE 3

__global__ __launch_bounds__(256, 2) void gemm_mma(
    const float* __restrict__ A, long long lda, long long sAh, long long sAb,
    const float* __restrict__ B, long long ldb, long long sBh, long long sBb,
    float* __restrict__ C, long long ldc, long long sCh, long long sCb,
    int K, const float* __restrict__ bias, int mode)
{
    const int bx = blockIdx.x, bz = blockIdx.z;
    int by = blockIdx.y;
    if (mode & 8) by = gridDim.y - 1 - by;
    if ((mode & 1) && bx > by) return;

    int NT = K >> 5;
    if (mode & 2) { int lim = (by + 1) * 4; if (lim < NT) NT = lim; }

    const int zb = bz / NH, zh = bz % NH;
    const float* Ab = A + (long long)zh * sAh + (long long)zb * sAb
                        + (long long)(by * 128) * lda;
    const float* Bb = B + (long long)zh * sBh + (long long)zb * sBb
                        + (long long)(bx * 128) * ldb;
    float* Cb = C + (long long)zh * sCh + (long long)zb * sCb;

    extern __shared__ float sm[];   // [3 stages][A(128x36) | B(128x36)]

    const int tid  = threadIdx.x;
    const int wid  = tid >> 5;
    const int lane = tid & 31;
    const int g    = lane >> 2;      // 0..7
    const int tq   = lane & 3;       // 0..3
    const int wr   = (wid >> 2) * 64;   // warp row origin
    const int wc   = (wid & 3) * 32;    // warp col origin

    float acc[4][4][4];
    #pragma unroll
    for (int i = 0; i < 4; i++)
        #pragma unroll
        for (int j = 0; j < 4; j++)
            #pragma unroll
            for (int f = 0; f < 4; f++) acc[i][j][f] = 0.f;

    const int lrow = tid >> 3;           // base row (128 rows, 8 chunks each)
    const int lcol = (tid & 7) * 4;      // float offset

    auto load_tile = [&](int t, int stage) {
        const int kt = t << 5;
        float* As = sm + stage * 2 * TILE_F;
        float* Bs = As + TILE_F;
        #pragma unroll
        for (int l = 0; l < 4; l++) {
            const int r = lrow + l * 32;
            cp_async16(smem_u32(&As[r * ASTR + lcol]),
                       Ab + (long long)r * lda + kt + lcol);
            cp_async16(smem_u32(&Bs[r * ASTR + lcol]),
                       Bb + (long long)r * ldb + kt + lcol);
        }
    };

    int aOff[4], bOff[4];
    #pragma unroll
    for (int i = 0; i < 4; i++) aOff[i] = (wr + i * 16 + g) * ASTR;
    #pragma unroll
    for (int j = 0; j < 4; j++) bOff[j] = (wc + j * 8 + g) * ASTR;

    // prologue: tiles 0 and 1 in flight (2 groups; empty group ok if NT==1)
    load_tile(0, 0);
    CP_COMMIT();
    if (NT > 1) load_tile(1, 1);
    CP_COMMIT();

    int stage = 0;
    for (int t = 0; t < NT; t++) {
        if (t + 1 < NT) { CP_WAIT(1); } else { CP_WAIT(0); }
        __syncthreads();   // tile t visible to all; all warps done with t-1

        // prefetch t+2 into buffer (t+2)%3 == (t-1)%3 (freed by the sync above)
        if (t + 2 < NT) {
            int ps = stage + 2; if (ps >= NSTAGE) ps -= NSTAGE;
            load_tile(t + 2, ps);
            CP_COMMIT();
        }

        const uint32_t* As = reinterpret_cast<const uint32_t*>(
            sm + stage * 2 * TILE_F);
        const uint32_t* Bs = As + TILE_F;

        #pragma unroll
        for (int ks = 0; ks < 4; ks++) {
            const int k0 = ks * 8 + tq;
            uint32_t af[4][4], bf[4][2];
            #pragma unroll
            for (int i = 0; i < 4; i++) {
                af[i][0] = As[aOff[i] + k0];
                af[i][1] = As[aOff[i] + 8 * ASTR + k0];
                af[i][2] = As[aOff[i] + k0 + 4];
                af[i][3] = As[aOff[i] + 8 * ASTR + k0 + 4];
            }
            #pragma unroll
            for (int j = 0; j < 4; j++) {
                bf[j][0] = Bs[bOff[j] + k0];
                bf[j][1] = Bs[bOff[j] + k0 + 4];
            }
            #pragma unroll
            for (int i = 0; i < 4; i++)
                #pragma unroll
                for (int j = 0; j < 4; j++)
                    mma_tf32(acc[i][j], af[i], bf[j]);
        }

        if (++stage >= NSTAGE) stage = 0;
    }

    const bool rnd = (mode & 4) != 0;
    #pragma unroll
    for (int i = 0; i < 4; i++) {
        const int r0 = by * 128 + wr + i * 16 + g;
        #pragma unroll
        for (int j = 0; j < 4; j++) {
            const int c0 = bx * 128 + wc + j * 8 + 2 * tq;
            float v0 = acc[i][j][0], v1 = acc[i][j][1];
            float v2 = acc[i][j][2], v3 = acc[i][j][3];
            if (bias) {
                const float b0 = bias[c0], b1 = bias[c0 + 1];
                v0 += b0; v1 += b1; v2 += b0; v3 += b1;
            }
            if (rnd) {
                v0 = rtf32(v0); v1 = rtf32(v1);
                v2 = rtf32(v2); v3 = rtf32(v3);
            }
            float2 p0; p0.x = v0; p0.y = v1;
            float2 p1; p1.x = v2; p1.y = v3;
            *reinterpret_cast<float2*>(Cb + (long long)r0 * ldc + c0) = p0;
            *reinterpret_cast<float2*>(Cb + (long long)(r0 + 8) * ldc + c0) = p1;
        }
    }
}

// ---------------------------------------------------------------------------
// Transpose + scale + tf32-round: out[c][r] = round(in[r][c] * mul)
// ---------------------------------------------------------------------------
__global__ void transpose_k(const float* __restrict__ in, float* __restrict__ out,
                            int R, int Cn, float mul)
{
    __shared__ float t[32][33];
    const int bx = blockIdx.x * 32, by = blockIdx.y * 32;
    const int tx = threadIdx.x, ty = threadIdx.y;
    #pragma unroll
    for (int yy = ty; yy < 32; yy += 8)
        t[yy][tx] = rtf32(in[(size_t)(by + yy) * Cn + bx + tx] * mul);
    __syncthreads();
    #pragma unroll
    for (int yy = ty; yy < 32; yy += 8)
        out[(size_t)(bx + yy) * R + by + tx] = t[tx][yy];
}

// ---------------------------------------------------------------------------
// Elementwise tf32-round copy (x -> xr), float4 vectorized
// ---------------------------------------------------------------------------
__global__ void round_copy(const float4* __restrict__ in, float4* __restrict__ out,
                           int n4)
{
    int i = blockIdx.x * blockDim.x + threadIdx.x;
    if (i < n4) {
        float4 v = in[i];
        v.x = rtf32(v.x); v.y = rtf32(v.y);
        v.z = rtf32(v.z); v.w = rtf32(v.w);
        out[i] = v;
    }
}

// ---------------------------------------------------------------------------
// Causal softmax over S rows (in place -> P, tf32-rounded), scale already
// folded into Wq. Zero-fill masked region up to the 128-block boundary.
// grid = (T, B*H), block = 256.  float4 loads (rows are 16B aligned).
// ---------------------------------------------------------------------------
__global__ __launch_bounds__(256) void softmax_causal(float* __restrict__ S)
{
    const int t  = blockIdx.x;
    const int bh = blockIdx.y;
    float* row = S + (size_t)bh * TT * TT + (size_t)t * TT;
    const int n   = t + 1;
    const int end = ((t >> 7) + 1) << 7;

    __shared__ float red[256];
    const int tid = threadIdx.x;

    float4 v[2];
    float mx = -1e30f;
    #pragma unroll
    for (int k = 0; k < 2; k++) {
        const int i = (tid + k * 256) * 4;
        float4 val = *reinterpret_cast<const float4*>(row + i);
        val.x = (i + 0 < n) ? val.x : -1e38f;
        val.y = (i + 1 < n) ? val.y : -1e38f;
        val.z = (i + 2 < n) ? val.z : -1e38f;
        val.w = (i + 3 < n) ? val.w : -1e38f;
        v[k] = val;
        mx = fmaxf(mx, fmaxf(fmaxf(val.x, val.y), fmaxf(val.z, val.w)));
    }
    red[tid] = mx;
    __syncthreads();
    for (int s = 128; s > 0; s >>= 1) {
        if (tid < s) red[tid] = fmaxf(red[tid], red[tid + s]);
        __syncthreads();
    }
    const float m = red[0];
    __syncthreads();

    float sum = 0.f;
    #pragma unroll
    for (int k = 0; k < 2; k++) {
        float4 e;
        e.x = __expf(v[k].x - m);
        e.y = __expf(v[k].y - m);
        e.z = __expf(v[k].z - m);
        e.w = __expf(v[k].w - m);
        v[k] = e;
        sum += e.x + e.y + e.z + e.w;   // exp(-1e38) == 0, safe to include
    }
    red[tid] = sum;
    __syncthreads();
    for (int s = 128; s > 0; s >>= 1) {
        if (tid < s) red[tid] += red[tid + s];
        __syncthreads();
    }
    const float inv = 1.0f / red[0];

    #pragma unroll
    for (int k = 0; k < 2; k++) {
        const int i = (tid + k * 256) * 4;
        if (i < end) {
            float4 o;
            o.x = rtf32(v[k].x * inv);
            o.y = rtf32(v[k].y * inv);
            o.z = rtf32(v[k].z * inv);
            o.w = rtf32(v[k].w * inv);
            *reinterpret_cast<float4*>(row + i) = o;
        }
    }
}

// ---------------------------------------------------------------------------
// Launch
// ---------------------------------------------------------------------------
extern "C" void kernel_launch(void* const* d_in, const int* in_sizes, int n_in,
                              void* d_out, int out_size)
{
    (void)in_sizes; (void)n_in; (void)out_size;
    const float* x  = (const float*)d_in[0];
    const float* Wq = (const float*)d_in[1];
    const float* Wc = (const float*)d_in[2];
    const float* Wk = (const float*)d_in[3];
    const float* Wv = (const float*)d_in[4];
    const float* Wo = (const float*)d_in[5];
    const float* bo = (const float*)d_in[6];
    float* out = (float*)d_out;

    float *xr, *q, *c, *k, *vt, *y, *s, *wqt, *wct, *wkt, *wvt, *wot;
    cudaGetSymbolAddress((void**)&xr, g_xr);
    cudaGetSymbolAddress((void**)&q,  g_q);
    cudaGetSymbolAddress((void**)&c,  g_c);
    cudaGetSymbolAddress((void**)&k,  g_k);
    cudaGetSymbolAddress((void**)&vt, g_vt);
    cudaGetSymbolAddress((void**)&y,  g_y);
    cudaGetSymbolAddress((void**)&s,  g_s);
    cudaGetSymbolAddress((void**)&wqt, g_wqt);
    cudaGetSymbolAddress((void**)&wct, g_wct);
    cudaGetSymbolAddress((void**)&wkt, g_wkt);
    cudaGetSymbolAddress((void**)&wvt, g_wvt);
    cudaGetSymbolAddress((void**)&wot, g_wot);

    const int gemm_smem = NSTAGE * 2 * TILE_F * (int)sizeof(float);  // 110592 B
    cudaFuncSetAttribute(gemm_mma,
                         cudaFuncAttributeMaxDynamicSharedMemorySize, gemm_smem);

    const float scale = 0.08838834764831845f;   // 1/sqrt(128), folded into WqT

    dim3 tb(32, 8);
    transpose_k<<<dim3(CC / 32, CC / 32), tb>>>(Wq, wqt, CC, CC, scale);
    transpose_k<<<dim3(DL / 32, CC / 32), tb>>>(Wc, wct, CC, DL, 1.f);
    transpose_k<<<dim3(CC / 32, DL / 32), tb>>>(Wk, wkt, DL, CC, 1.f);
    transpose_k<<<dim3(CC / 32, DL / 32), tb>>>(Wv, wvt, DL, CC, 1.f);
    transpose_k<<<dim3(CC / 32, CC / 32), tb>>>(Wo, wot, CC, CC, 1.f);

    round_copy<<<(BT * CC / 4 + 255) / 256, 256>>>(
        (const float4*)x, (float4*)xr, BT * CC / 4);

    dim3 blk(256);

    // q = xr @ Wq' (scale folded), rounded
    gemm_mma<<<dim3(CC / 128, BT / 128, 1), blk, gemm_smem>>>(
        xr, CC, 0, 0, wqt, CC, 0, 0, q, CC, 0, 0, CC, nullptr, 4);
    // c = xr @ Wc, rounded
    gemm_mma<<<dim3(DL / 128, BT / 128, 1), blk, gemm_smem>>>(
        xr, CC, 0, 0, wct, CC, 0, 0, c, DL, 0, 0, CC, nullptr, 4);
    // k = c @ Wk, rounded
    gemm_mma<<<dim3(CC / 128, BT / 128, 1), blk, gemm_smem>>>(
        c, DL, 0, 0, wkt, DL, 0, 0, k, CC, 0, 0, DL, nullptr, 4);
    // vT = Wv^T . c^T -> vt[CC, BT], rounded
    gemm_mma<<<dim3(BT / 128, CC / 128, 1), blk, gemm_smem>>>(
        wvt, DL, 0, 0, c, DL, 0, 0, vt, BT, 0, 0, DL, nullptr, 4);

    // S = Q_h . K_h^T per (b,h)   [causal block skip], NOT rounded
    gemm_mma<<<dim3(TT / 128, TT / 128, BHN), blk, gemm_smem>>>(
        q, CC, HSD, (long long)TT * CC,
        k, CC, HSD, (long long)TT * CC,
        s, TT, (long long)TT * TT, (long long)NH * TT * TT,
        HSD, nullptr, 1);

    // softmax (in place, writes rounded P)
    softmax_causal<<<dim3(TT, BHN), blk>>>(s);

    // O = P . V^T   [causal K limit, heavy blocks first], rounded
    gemm_mma<<<dim3(HSD / 128, TT / 128, BHN), blk, gemm_smem>>>(
        s, TT, (long long)TT * TT, (long long)NH * TT * TT,
        vt, BT, (long long)HSD * BT, TT,
        y, CC, HSD, (long long)TT * CC,
        TT, nullptr, 2 | 4 | 8);

    // out = y @ Wo + bo   (full fp32 epilogue)
    gemm_mma<<<dim3(CC / 128, BT / 128, 1), blk, gemm_smem>>>(
        y, CC, 0, 0, wot, CC, 0, 0, out, CC, 0, 0, CC, bo, 0);
}

// round 11
// speedup vs baseline: 5.0360x; 1.4691x over previous
#include <cuda_runtime.h>
#include <cuda_fp16.h>
#include <cstdint>

// ---------------------------------------------------------------------------
// Problem constants
// ---------------------------------------------------------------------------
#define BB 2
#define TT 2048
#define CC 2048
#define NH 16
#define HSD 128
#define DL 1024
#define BT (BB * TT)      // 4096
#define BHN (BB * NH)     // 32

// ---------------------------------------------------------------------------
// Scratch (__device__ globals; no cudaMalloc allowed)
// ---------------------------------------------------------------------------
__device__ __half g_xh[BT * CC];        // fp16 copy of x
__device__ __half g_q[BT * CC];
__device__ __half g_c[BT * DL];
__device__ __half g_k[BT * CC];
__device__ __half g_vt[CC * BT];        // v transposed: [C][B*T]
__device__ __half g_y[BT * CC];
__device__ float  g_s[134217728];       // 512MB scores: [BH][T][T] fp32
__device__ __half g_p[134217728];       // 256MB probs (half)
__device__ __half g_wqt[CC * CC];
__device__ __half g_wct[DL * CC];
__device__ __half g_wkt[CC * DL];
__device__ __half g_wvt[CC * DL];
__device__ __half g_wot[CC * CC];

// ---------------------------------------------------------------------------
// Helpers (portable PTX: cp.async + mma.sync fp16, sm_80+)
// ---------------------------------------------------------------------------
__device__ __forceinline__ uint32_t smem_u32(const void* p) {
    uint32_t a;
    asm("{ .reg .u64 t; cvta.to.shared.u64 t, %1; cvt.u32.u64 %0, t; }"
        : "=r"(a) : "l"(p));
    return a;
}

__device__ __forceinline__ void cp_async16(uint32_t dst, const void* src) {
    asm volatile("cp.async.cg.shared.global [%0], [%1], 16;"
                 :: "r"(dst), "l"(src));
}
#define CP_COMMIT() asm volatile("cp.async.commit_group;" ::: "memory")
#define CP_WAIT(n)  asm volatile("cp.async.wait_group %0;" :: "n"(n) : "memory")

__device__ __forceinline__ void mma_f16(float c[4], const uint32_t a[4],
                                        const uint32_t b[2]) {
    asm volatile(
        "mma.sync.aligned.m16n8k16.row.col.f32.f16.f16.f32 "
        "{%0,%1,%2,%3}, {%4,%5,%6,%7}, {%8,%9}, {%0,%1,%2,%3};"
        : "+f"(c[0]), "+f"(c[1]), "+f"(c[2]), "+f"(c[3])
        : "r"(a[0]), "r"(a[1]), "r"(a[2]), "r"(a[3]), "r"(b[0]), "r"(b[1]));
}

// ---------------------------------------------------------------------------
// fp16 warp-MMA GEMM (fp32 accum):  D[m][n] = sum_k A[m][k] * B[n][k]
// CTA tile 128x128, K-tile 32, 8 warps (2x4), 64x32/warp, m16n8k16 frags.
// 3-stage cp.async ring, ONE __syncthreads per K-iteration, 2 CTAs/SM.
// mode bit0: causal block skip   bit1: causal K limit (PV)
// mode bit2: write HALF output   bit3: reverse by (heavy blocks first)
// Strides in ELEMENTS (halves).
// ---------------------------------------------------------------------------
#define ASTR 40                       // halves per smem row (80B: banks coprime)
#define TILE_H (128 * ASTR)           // halves per 128x32 tile (padded)
#define NSTAGE 3

__global__ __launch_bounds__(256, 2) void gemm_mma(
    const __half* __restrict__ A, long long lda, long long sAh, long long sAb,
    const __half* __restrict__ B, long long ldb, long long sBh, long long sBb,
    void* __restrict__ Cv, long long ldc, long long sCh, long long sCb,
    int K, const float* __restrict__ bias, int mode)
{
    const int bx = blockIdx.x, bz = blockIdx.z;
    int by = blockIdx.y;
    if (mode & 8) by = gridDim.y - 1 - by;
    if ((mode & 1) && bx > by) return;

    int NT = K >> 5;
    if (mode & 2) { int lim = (by + 1) * 4; if (lim < NT) NT = lim; }

    const int zb = bz / NH, zh = bz % NH;
    const __half* Ab = A + (long long)zh * sAh + (long long)zb * sAb
                         + (long long)(by * 128) * lda;
    const __half* Bb = B + (long long)zh * sBh + (long long)zb * sBb
                         + (long long)(bx * 128) * ldb;

    extern __shared__ __half sm[];   // [3 stages][A(128x40) | B(128x40)]

    const int tid  = threadIdx.x;
    const int wid  = tid >> 5;
    const int lane = tid & 31;
    const int g    = lane >> 2;      // 0..7
    const int tq   = lane & 3;       // 0..3
    const int wr   = (wid >> 2) * 64;   // warp row origin
    const int wc   = (wid & 3) * 32;    // warp col origin

    float acc[4][4][4];
    #pragma unroll
    for (int i = 0; i < 4; i++)
        #pragma unroll
        for (int j = 0; j < 4; j++)
            #pragma unroll
            for (int f = 0; f < 4; f++) acc[i][j][f] = 0.f;

    // loader: 128 rows x 4 16B-chunks per operand = 512 chunks; 2/thread
    const int lr0 = tid >> 2;            // row for l=0 (0..63)... ci>>2
    const int lc0 = (tid & 3) * 8;       // half offset of 16B chunk

    auto load_tile = [&](int t, int stage) {
        const int kt = t << 5;
        __half* As = sm + stage * 2 * TILE_H;
        __half* Bs = As + TILE_H;
        #pragma unroll
        for (int l = 0; l < 2; l++) {
            const int r = lr0 + l * 64;
            cp_async16(smem_u32(&As[r * ASTR + lc0]),
                       Ab + (long long)r * lda + kt + lc0);
            cp_async16(smem_u32(&Bs[r * ASTR + lc0]),
                       Bb + (long long)r * ldb + kt + lc0);
        }
    };

    // fragment row offsets in uint32 units (ASTR/2 = 20 u32 per row)
    int aOff[4], bOff[4];
    #pragma unroll
    for (int i = 0; i < 4; i++) aOff[i] = (wr + i * 16 + g) * (ASTR / 2);
    #pragma unroll
    for (int j = 0; j < 4; j++) bOff[j] = (wc + j * 8 + g) * (ASTR / 2);

    load_tile(0, 0);
    CP_COMMIT();
    if (NT > 1) load_tile(1, 1);
    CP_COMMIT();

    int stage = 0;
    for (int t = 0; t < NT; t++) {
        if (t + 1 < NT) { CP_WAIT(1); } else { CP_WAIT(0); }
        __syncthreads();   // tile t visible; all warps done with t-1

        if (t + 2 < NT) {
            int ps = stage + 2; if (ps >= NSTAGE) ps -= NSTAGE;
            load_tile(t + 2, ps);
            CP_COMMIT();
        }

        const uint32_t* As = reinterpret_cast<const uint32_t*>(
            sm + stage * 2 * TILE_H);
        const uint32_t* Bs = As + TILE_H / 2;

        #pragma unroll
        for (int ks = 0; ks < 2; ks++) {     // two k16 steps cover K-tile 32
            const int k0 = ks * 8 + tq;      // u32 index within row
            uint32_t af[4][4], bf[4][2];
            #pragma unroll
            for (int i = 0; i < 4; i++) {
                af[i][0] = As[aOff[i] + k0];                    // row g,   k..k+1
                af[i][1] = As[aOff[i] + 8 * (ASTR / 2) + k0];   // row g+8
                af[i][2] = As[aOff[i] + k0 + 4];                // row g,   k+8..9
                af[i][3] = As[aOff[i] + 8 * (ASTR / 2) + k0 + 4];
            }
            #pragma unroll
            for (int j = 0; j < 4; j++) {
                bf[j][0] = Bs[bOff[j] + k0];
                bf[j][1] = Bs[bOff[j] + k0 + 4];
            }
            #pragma unroll
            for (int i = 0; i < 4; i++)
                #pragma unroll
                for (int j = 0; j < 4; j++)
                    mma_f16(acc[i][j], af[i], bf[j]);
        }

        if (++stage >= NSTAGE) stage = 0;
    }

    // epilogue
    if (mode & 4) {   // half output
        __half* Cb = (__half*)Cv + (long long)zh * sCh + (long long)zb * sCb;
        #pragma unroll
        for (int i = 0; i < 4; i++) {
            const int r0 = by * 128 + wr + i * 16 + g;
            #pragma unroll
            for (int j = 0; j < 4; j++) {
                const int c0 = bx * 128 + wc + j * 8 + 2 * tq;
                __half2 h0 = __floats2half2_rn(acc[i][j][0], acc[i][j][1]);
                __half2 h1 = __floats2half2_rn(acc[i][j][2], acc[i][j][3]);
                *reinterpret_cast<__half2*>(Cb + (long long)r0 * ldc + c0) = h0;
                *reinterpret_cast<__half2*>(Cb + (long long)(r0 + 8) * ldc + c0) = h1;
            }
        }
    } else {          // float output (+bias)
        float* Cb = (float*)Cv + (long long)zh * sCh + (long long)zb * sCb;
        #pragma unroll
        for (int i = 0; i < 4; i++) {
            const int r0 = by * 128 + wr + i * 16 + g;
            #pragma unroll
            for (int j = 0; j < 4; j++) {
                const int c0 = bx * 128 + wc + j * 8 + 2 * tq;
                float v0 = acc[i][j][0], v1 = acc[i][j][1];
                float v2 = acc[i][j][2], v3 = acc[i][j][3];
                if (bias) {
                    const float b0 = bias[c0], b1 = bias[c0 + 1];
                    v0 += b0; v1 += b1; v2 += b0; v3 += b1;
                }
                float2 p0; p0.x = v0; p0.y = v1;
                float2 p1; p1.x = v2; p1.y = v3;
                *reinterpret_cast<float2*>(Cb + (long long)r0 * ldc + c0) = p0;
                *reinterpret_cast<float2*>(Cb + (long long)(r0 + 8) * ldc + c0) = p1;
            }
        }
    }
}

// ---------------------------------------------------------------------------
// Transpose + scale -> fp16: out[c][r] = half(in[r][c] * mul)
// ---------------------------------------------------------------------------
__global__ void transpose_k(const float* __restrict__ in, __half* __restrict__ out,
                            int R, int Cn, float mul)
{
    __shared__ float t[32][33];
    const int bx = blockIdx.x * 32, by = blockIdx.y * 32;
    const int tx = threadIdx.x, ty = threadIdx.y;
    #pragma unroll
    for (int yy = ty; yy < 32; yy += 8)
        t[yy][tx] = in[(size_t)(by + yy) * Cn + bx + tx] * mul;
    __syncthreads();
    #pragma unroll
    for (int yy = ty; yy < 32; yy += 8)
        out[(size_t)(bx + yy) * R + by + tx] = __float2half_rn(t[tx][yy]);
}

// ---------------------------------------------------------------------------
// float4 -> 4 halves convert (x -> xh)
// ---------------------------------------------------------------------------
__global__ void conv_half(const float4* __restrict__ in, __half2* __restrict__ out,
                          int n4)
{
    int i = blockIdx.x * blockDim.x + threadIdx.x;
    if (i < n4) {
        float4 v = in[i];
        out[2 * i + 0] = __floats2half2_rn(v.x, v.y);
        out[2 * i + 1] = __floats2half2_rn(v.z, v.w);
    }
}

// ---------------------------------------------------------------------------
// Causal softmax: read fp32 S row, write fp16 P row (zero-filled to the
// 128-block edge). Scale already folded into Wq. grid = (T, B*H), block 256.
// ---------------------------------------------------------------------------
__global__ __launch_bounds__(256) void softmax_causal(
    const float* __restrict__ S, __half* __restrict__ P)
{
    const int t  = blockIdx.x;
    const int bh = blockIdx.y;
    const float* row = S + (size_t)bh * TT * TT + (size_t)t * TT;
    __half* rowp = P + (size_t)bh * TT * TT + (size_t)t * TT;
    const int n   = t + 1;
    const int end = ((t >> 7) + 1) << 7;

    __shared__ float red[256];
    const int tid = threadIdx.x;

    float4 v[2];
    float mx = -1e30f;
    #pragma unroll
    for (int k = 0; k < 2; k++) {
        const int i = (tid + k * 256) * 4;
        float4 val = *reinterpret_cast<const float4*>(row + i);
        val.x = (i + 0 < n) ? val.x : -1e38f;
        val.y = (i + 1 < n) ? val.y : -1e38f;
        val.z = (i + 2 < n) ? val.z : -1e38f;
        val.w = (i + 3 < n) ? val.w : -1e38f;
        v[k] = val;
        mx = fmaxf(mx, fmaxf(fmaxf(val.x, val.y), fmaxf(val.z, val.w)));
    }
    red[tid] = mx;
    __syncthreads();
    for (int s = 128; s > 0; s >>= 1) {
        if (tid < s) red[tid] = fmaxf(red[tid], red[tid + s]);
        __syncthreads();
    }
    const float m = red[0];
    __syncthreads();

    float sum = 0.f;
    #pragma unroll
    for (int k = 0; k < 2; k++) {
        float4 e;
        e.x = __expf(v[k].x - m);
        e.y = __expf(v[k].y - m);
        e.z = __expf(v[k].z - m);
        e.w = __expf(v[k].w - m);
        v[k] = e;
        sum += e.x + e.y + e.z + e.w;   // exp(-1e38) == 0
    }
    red[tid] = sum;
    __syncthreads();
    for (int s = 128; s > 0; s >>= 1) {
        if (tid < s) red[tid] += red[tid + s];
        __syncthreads();
    }
    const float inv = 1.0f / red[0];

    #pragma unroll
    for (int k = 0; k < 2; k++) {
        const int i = (tid + k * 256) * 4;
        if (i < end) {
            __half2 h0 = __floats2half2_rn(v[k].x * inv, v[k].y * inv);
            __half2 h1 = __floats2half2_rn(v[k].z * inv, v[k].w * inv);
            *reinterpret_cast<__half2*>(rowp + i)     = h0;
            *reinterpret_cast<__half2*>(rowp + i + 2) = h1;
        }
    }
}

// ---------------------------------------------------------------------------
// Launch
// ---------------------------------------------------------------------------
extern "C" void kernel_launch(void* const* d_in, const int* in_sizes, int n_in,
                              void* d_out, int out_size)
{
    (void)in_sizes; (void)n_in; (void)out_size;
    const float* x  = (const float*)d_in[0];
    const float* Wq = (const float*)d_in[1];
    const float* Wc = (const float*)d_in[2];
    const float* Wk = (const float*)d_in[3];
    const float* Wv = (const float*)d_in[4];
    const float* Wo = (const float*)d_in[5];
    const float* bo = (const float*)d_in[6];
    float* out = (float*)d_out;

    __half *xh, *q, *c, *k, *vt, *y, *p, *wqt, *wct, *wkt, *wvt, *wot;
    float *s;
    cudaGetSymbolAddress((void**)&xh, g_xh);
    cudaGetSymbolAddress((void**)&q,  g_q);
    cudaGetSymbolAddress((void**)&c,  g_c);
    cudaGetSymbolAddress((void**)&k,  g_k);
    cudaGetSymbolAddress((void**)&vt, g_vt);
    cudaGetSymbolAddress((void**)&y,  g_y);
    cudaGetSymbolAddress((void**)&s,  g_s);
    cudaGetSymbolAddress((void**)&p,  g_p);
    cudaGetSymbolAddress((void**)&wqt, g_wqt);
    cudaGetSymbolAddress((void**)&wct, g_wct);
    cudaGetSymbolAddress((void**)&wkt, g_wkt);
    cudaGetSymbolAddress((void**)&wvt, g_wvt);
    cudaGetSymbolAddress((void**)&wot, g_wot);

    const int gemm_smem = NSTAGE * 2 * TILE_H * (int)sizeof(__half);  // 61440 B
    cudaFuncSetAttribute(gemm_mma,
                         cudaFuncAttributeMaxDynamicSharedMemorySize, gemm_smem);

    const float scale = 0.08838834764831845f;   // 1/sqrt(128), folded into WqT

    dim3 tb(32, 8);
    transpose_k<<<dim3(CC / 32, CC / 32), tb>>>(Wq, wqt, CC, CC, scale);
    transpose_k<<<dim3(DL / 32, CC / 32), tb>>>(Wc, wct, CC, DL, 1.f);
    transpose_k<<<dim3(CC / 32, DL / 32), tb>>>(Wk, wkt, DL, CC, 1.f);
    transpose_k<<<dim3(CC / 32, DL / 32), tb>>>(Wv, wvt, DL, CC, 1.f);
    transpose_k<<<dim3(CC / 32, CC / 32), tb>>>(Wo, wot, CC, CC, 1.f);

    conv_half<<<(BT * CC / 4 + 255) / 256, 256>>>(
        (const float4*)x, (__half2*)xh, BT * CC / 4);

    dim3 blk(256);

    // q = xh @ Wq' (scale folded), half out
    gemm_mma<<<dim3(CC / 128, BT / 128, 1), blk, gemm_smem>>>(
        xh, CC, 0, 0, wqt, CC, 0, 0, q, CC, 0, 0, CC, nullptr, 4);
    // c = xh @ Wc, half out
    gemm_mma<<<dim3(DL / 128, BT / 128, 1), blk, gemm_smem>>>(
        xh, CC, 0, 0, wct, CC, 0, 0, c, DL, 0, 0, CC, nullptr, 4);
    // k = c @ Wk, half out
    gemm_mma<<<dim3(CC / 128, BT / 128, 1), blk, gemm_smem>>>(
        c, DL, 0, 0, wkt, DL, 0, 0, k, CC, 0, 0, DL, nullptr, 4);
    // vT = Wv^T . c^T -> vt[CC, BT], half out
    gemm_mma<<<dim3(BT / 128, CC / 128, 1), blk, gemm_smem>>>(
        wvt, DL, 0, 0, c, DL, 0, 0, vt, BT, 0, 0, DL, nullptr, 4);

    // S = Q_h . K_h^T per (b,h)  [causal block skip], fp32 out
    gemm_mma<<<dim3(TT / 128, TT / 128, BHN), blk, gemm_smem>>>(
        q, CC, HSD, (long long)TT * CC,
        k, CC, HSD, (long long)TT * CC,
        s, TT, (long long)TT * TT, (long long)NH * TT * TT,
        HSD, nullptr, 1);

    // softmax: S (fp32) -> P (half)
    softmax_causal<<<dim3(TT, BHN), blk>>>(s, p);

    // O = P . V^T  [causal K limit, heavy blocks first], half out
    gemm_mma<<<dim3(HSD / 128, TT / 128, BHN), blk, gemm_smem>>>(
        p, TT, (long long)TT * TT, (long long)NH * TT * TT,
        vt, BT, (long long)HSD * BT, TT,
        y, CC, HSD, (long long)TT * CC,
        TT, nullptr, 2 | 4 | 8);

    // out = y @ Wo + bo   (fp32 epilogue)
    gemm_mma<<<dim3(CC / 128, BT / 128, 1), blk, gemm_smem>>>(
        y, CC, 0, 0, wot, CC, 0, 0, out, CC, 0, 0, CC, bo, 0);
}

// round 16
// speedup vs baseline: 5.6382x; 1.1196x over previous
#include <cuda_runtime.h>
#include <cuda_fp16.h>
#include <cstdint>

// ---------------------------------------------------------------------------
// Problem constants
// ---------------------------------------------------------------------------
#define BB 2
#define TT 2048
#define CC 2048
#define NH 16
#define HSD 128
#define DL 1024
#define BT (BB * TT)      // 4096
#define BHN (BB * NH)     // 32

// ---------------------------------------------------------------------------
// Scratch (__device__ globals; no cudaMalloc allowed)
// ---------------------------------------------------------------------------
__device__ __half g_xh[BT * CC];        // fp16 copy of x
__device__ __half g_q[BT * CC];
__device__ __half g_c[BT * DL];
__device__ __half g_k[BT * CC];
__device__ __half g_vt[CC * BT];        // v transposed: [C][B*T]
__device__ __half g_y[BT * CC];
__device__ float  g_s[134217728];       // 512MB scores: [BH][T][T] fp32
__device__ __half g_p[134217728];       // 256MB probs (half)
__device__ __half g_wqt[CC * CC];
__device__ __half g_wct[DL * CC];
__device__ __half g_wkt[CC * DL];
__device__ __half g_wvt[CC * DL];
__device__ __half g_wot[CC * CC];

// ---------------------------------------------------------------------------
// Helpers (portable PTX: cp.async + ldmatrix + mma.sync fp16, sm_80+)
// ---------------------------------------------------------------------------
__device__ __forceinline__ uint32_t smem_u32(const void* p) {
    uint32_t a;
    asm("{ .reg .u64 t; cvta.to.shared.u64 t, %1; cvt.u32.u64 %0, t; }"
        : "=r"(a) : "l"(p));
    return a;
}

__device__ __forceinline__ void cp_async16(uint32_t dst, const void* src) {
    asm volatile("cp.async.cg.shared.global [%0], [%1], 16;"
                 :: "r"(dst), "l"(src));
}
#define CP_COMMIT() asm volatile("cp.async.commit_group;" ::: "memory")
#define CP_WAIT(n)  asm volatile("cp.async.wait_group %0;" :: "n"(n) : "memory")

#define LDSM_X4(r0, r1, r2, r3, addr)                                         \
    asm volatile("ldmatrix.sync.aligned.m8n8.x4.shared.b16 {%0,%1,%2,%3}, [%4];" \
                 : "=r"(r0), "=r"(r1), "=r"(r2), "=r"(r3) : "r"(addr))

__device__ __forceinline__ void mma_f16(float c[4], const uint32_t a[4],
                                        const uint32_t b[2]) {
    asm volatile(
        "mma.sync.aligned.m16n8k16.row.col.f32.f16.f16.f32 "
        "{%0,%1,%2,%3}, {%4,%5,%6,%7}, {%8,%9}, {%0,%1,%2,%3};"
        : "+f"(c[0]), "+f"(c[1]), "+f"(c[2]), "+f"(c[3])
        : "r"(a[0]), "r"(a[1]), "r"(a[2]), "r"(a[3]), "r"(b[0]), "r"(b[1]));
}

// ---------------------------------------------------------------------------
// fp16 warp-MMA GEMM (fp32 accum):  D[m][n] = sum_k A[m][k] * B[n][k]
// CTA tile 128x128, K-tile 32, 8 warps (2x4), 64x32/warp, m16n8k16 frags.
// ldmatrix.x4 fragment loads; 3-stage cp.async ring; ONE sync/K-iter; 2 CTAs/SM.
// mode bit0: causal block skip   bit1: causal K limit (PV)
// mode bit2: write HALF output   bit3: reverse by (heavy blocks first)
// Strides in ELEMENTS (halves).
// ---------------------------------------------------------------------------
#define ASTR 40                       // halves per smem row (80B: ldmatrix-safe)
#define TILE_H (128 * ASTR)           // halves per 128x32 tile (padded)
#define NSTAGE 3

__global__ __launch_bounds__(256, 2) void gemm_mma(
    const __half* __restrict__ A, long long lda, long long sAh, long long sAb,
    const __half* __restrict__ B, long long ldb, long long sBh, long long sBb,
    void* __restrict__ Cv, long long ldc, long long sCh, long long sCb,
    int K, const float* __restrict__ bias, int mode)
{
    const int bx = blockIdx.x, bz = blockIdx.z;
    int by = blockIdx.y;
    if (mode & 8) by = gridDim.y - 1 - by;
    if ((mode & 1) && bx > by) return;

    int NT = K >> 5;
    if (mode & 2) { int lim = (by + 1) * 4; if (lim < NT) NT = lim; }

    const int zb = bz / NH, zh = bz % NH;
    const __half* Ab = A + (long long)zh * sAh + (long long)zb * sAb
                         + (long long)(by * 128) * lda;
    const __half* Bb = B + (long long)zh * sBh + (long long)zb * sBb
                         + (long long)(bx * 128) * ldb;

    extern __shared__ __half sm[];   // [3 stages][A(128x40) | B(128x40)]

    const int tid  = threadIdx.x;
    const int wid  = tid >> 5;
    const int lane = tid & 31;
    const int g    = lane >> 2;      // 0..7
    const int tq   = lane & 3;       // 0..3
    const int wr   = (wid >> 2) * 64;   // warp row origin
    const int wc   = (wid & 3) * 32;    // warp col origin

    float acc[4][4][4];
    #pragma unroll
    for (int i = 0; i < 4; i++)
        #pragma unroll
        for (int j = 0; j < 4; j++)
            #pragma unroll
            for (int f = 0; f < 4; f++) acc[i][j][f] = 0.f;

    // loader: 128 rows x 4 16B-chunks per operand = 512 chunks; 2/thread
    const int lr0 = tid >> 2;            // row (0..63)
    const int lc0 = (tid & 3) * 8;       // half offset of 16B chunk

    auto load_tile = [&](int t, int stage) {
        const int kt = t << 5;
        __half* As = sm + stage * 2 * TILE_H;
        __half* Bs = As + TILE_H;
        #pragma unroll
        for (int l = 0; l < 2; l++) {
            const int r = lr0 + l * 64;
            cp_async16(smem_u32(&As[r * ASTR + lc0]),
                       Ab + (long long)r * lda + kt + lc0);
            cp_async16(smem_u32(&Bs[r * ASTR + lc0]),
                       Bb + (long long)r * ldb + kt + lc0);
        }
    };

    // ldmatrix per-thread half-offsets (within a tile)
    // A (m-tile i): lanes 0-15 -> rows wr+i*16+lane (k+0); 16-31 -> same rows, k+8
    // B (pair jj): m0=(n rows, k0) m1=(n, k8) m2=(n+8, k0) m3=(n+8, k8)
    const uint32_t smbase = smem_u32(sm);
    int aoffH[4], boffH[2];
    #pragma unroll
    for (int i = 0; i < 4; i++)
        aoffH[i] = (wr + i * 16 + (lane & 15)) * ASTR + ((lane >> 4) << 3);
    #pragma unroll
    for (int jj = 0; jj < 2; jj++)
        boffH[jj] = (wc + jj * 16 + ((lane >> 4) << 3) + (lane & 7)) * ASTR
                  + (((lane >> 3) & 1) << 3);

    load_tile(0, 0);
    CP_COMMIT();
    if (NT > 1) load_tile(1, 1);
    CP_COMMIT();

    int stage = 0;
    for (int t = 0; t < NT; t++) {
        if (t + 1 < NT) { CP_WAIT(1); } else { CP_WAIT(0); }
        __syncthreads();   // tile t visible; all warps done with t-1

        if (t + 2 < NT) {
            int ps = stage + 2; if (ps >= NSTAGE) ps -= NSTAGE;
            load_tile(t + 2, ps);
            CP_COMMIT();
        }

        const uint32_t tbase = smbase + (uint32_t)(stage * 2 * TILE_H * 2);

        #pragma unroll
        for (int ks = 0; ks < 2; ks++) {     // two k16 steps cover K-tile 32
            uint32_t af[4][4], bf[4][2];
            #pragma unroll
            for (int i = 0; i < 4; i++) {
                uint32_t ad = tbase + (uint32_t)((aoffH[i] + ks * 16) * 2);
                LDSM_X4(af[i][0], af[i][1], af[i][2], af[i][3], ad);
            }
            #pragma unroll
            for (int jj = 0; jj < 2; jj++) {
                uint32_t bd = tbase + (uint32_t)(TILE_H * 2)
                            + (uint32_t)((boffH[jj] + ks * 16) * 2);
                LDSM_X4(bf[2 * jj][0], bf[2 * jj][1],
                        bf[2 * jj + 1][0], bf[2 * jj + 1][1], bd);
            }
            #pragma unroll
            for (int i = 0; i < 4; i++)
                #pragma unroll
                for (int j = 0; j < 4; j++)
                    mma_f16(acc[i][j], af[i], bf[j]);
        }

        if (++stage >= NSTAGE) stage = 0;
    }

    // epilogue
    if (mode & 4) {   // half output
        __half* Cb = (__half*)Cv + (long long)zh * sCh + (long long)zb * sCb;
        #pragma unroll
        for (int i = 0; i < 4; i++) {
            const int r0 = by * 128 + wr + i * 16 + g;
            #pragma unroll
            for (int j = 0; j < 4; j++) {
                const int c0 = bx * 128 + wc + j * 8 + 2 * tq;
                __half2 h0 = __floats2half2_rn(acc[i][j][0], acc[i][j][1]);
                __half2 h1 = __floats2half2_rn(acc[i][j][2], acc[i][j][3]);
                *reinterpret_cast<__half2*>(Cb + (long long)r0 * ldc + c0) = h0;
                *reinterpret_cast<__half2*>(Cb + (long long)(r0 + 8) * ldc + c0) = h1;
            }
        }
    } else {          // float output (+bias)
        float* Cb = (float*)Cv + (long long)zh * sCh + (long long)zb * sCb;
        #pragma unroll
        for (int i = 0; i < 4; i++) {
            const int r0 = by * 128 + wr + i * 16 + g;
            #pragma unroll
            for (int j = 0; j < 4; j++) {
                const int c0 = bx * 128 + wc + j * 8 + 2 * tq;
                float v0 = acc[i][j][0], v1 = acc[i][j][1];
                float v2 = acc[i][j][2], v3 = acc[i][j][3];
                if (bias) {
                    const float b0 = bias[c0], b1 = bias[c0 + 1];
                    v0 += b0; v1 += b1; v2 += b0; v3 += b1;
                }
                float2 p0; p0.x = v0; p0.y = v1;
                float2 p1; p1.x = v2; p1.y = v3;
                *reinterpret_cast<float2*>(Cb + (long long)r0 * ldc + c0) = p0;
                *reinterpret_cast<float2*>(Cb + (long long)(r0 + 8) * ldc + c0) = p1;
            }
        }
    }
}

// ---------------------------------------------------------------------------
// Transpose + scale -> fp16: out[c][r] = half(in[r][c] * mul)
// ---------------------------------------------------------------------------
__global__ void transpose_k(const float* __restrict__ in, __half* __restrict__ out,
                            int R, int Cn, float mul)
{
    __shared__ float t[32][33];
    const int bx = blockIdx.x * 32, by = blockIdx.y * 32;
    const int tx = threadIdx.x, ty = threadIdx.y;
    #pragma unroll
    for (int yy = ty; yy < 32; yy += 8)
        t[yy][tx] = in[(size_t)(by + yy) * Cn + bx + tx] * mul;
    __syncthreads();
    #pragma unroll
    for (int yy = ty; yy < 32; yy += 8)
        out[(size_t)(bx + yy) * R + by + tx] = __float2half_rn(t[tx][yy]);
}

// ---------------------------------------------------------------------------
// float4 -> 4 halves convert (x -> xh)
// ---------------------------------------------------------------------------
__global__ void conv_half(const float4* __restrict__ in, __half2* __restrict__ out,
                          int n4)
{
    int i = blockIdx.x * blockDim.x + threadIdx.x;
    if (i < n4) {
        float4 v = in[i];
        out[2 * i + 0] = __floats2half2_rn(v.x, v.y);
        out[2 * i + 1] = __floats2half2_rn(v.z, v.w);
    }
}

// ---------------------------------------------------------------------------
// Causal softmax: read fp32 S row (ONLY the live 128-block prefix), write
// fp16 P row zero-filled to the 128-block edge. Scale folded into Wq.
// grid = (T, B*H), block = 256.
// ---------------------------------------------------------------------------
__global__ __launch_bounds__(256) void softmax_causal(
    const float* __restrict__ S, __half* __restrict__ P)
{
    const int t  = blockIdx.x;
    const int bh = blockIdx.y;
    const float* row = S + (size_t)bh * TT * TT + (size_t)t * TT;
    __half* rowp = P + (size_t)bh * TT * TT + (size_t)t * TT;
    const int n   = t + 1;
    const int end = ((t >> 7) + 1) << 7;

    __shared__ float red[256];
    const int tid = threadIdx.x;

    float4 v[2];
    float mx = -1e30f;
    #pragma unroll
    for (int k = 0; k < 2; k++) {
        const int i = (tid + k * 256) * 4;
        if (i < end) {
            float4 val = *reinterpret_cast<const float4*>(row + i);
            val.x = (i + 0 < n) ? val.x : -1e38f;
            val.y = (i + 1 < n) ? val.y : -1e38f;
            val.z = (i + 2 < n) ? val.z : -1e38f;
            val.w = (i + 3 < n) ? val.w : -1e38f;
            v[k] = val;
            mx = fmaxf(mx, fmaxf(fmaxf(val.x, val.y), fmaxf(val.z, val.w)));
        } else {
            v[k].x = v[k].y = v[k].z = v[k].w = -1e38f;
        }
    }
    red[tid] = mx;
    __syncthreads();
    for (int s = 128; s > 0; s >>= 1) {
        if (tid < s) red[tid] = fmaxf(red[tid], red[tid + s]);
        __syncthreads();
    }
    const float m = red[0];
    __syncthreads();

    float sum = 0.f;
    #pragma unroll
    for (int k = 0; k < 2; k++) {
        float4 e;
        e.x = __expf(v[k].x - m);
        e.y = __expf(v[k].y - m);
        e.z = __expf(v[k].z - m);
        e.w = __expf(v[k].w - m);
        v[k] = e;
        sum += e.x + e.y + e.z + e.w;   // exp(-1e38) == 0
    }
    red[tid] = sum;
    __syncthreads();
    for (int s = 128; s > 0; s >>= 1) {
        if (tid < s) red[tid] += red[tid + s];
        __syncthreads();
    }
    const float inv = 1.0f / red[0];

    #pragma unroll
    for (int k = 0; k < 2; k++) {
        const int i = (tid + k * 256) * 4;
        if (i < end) {
            __half2 h0 = __floats2half2_rn(v[k].x * inv, v[k].y * inv);
            __half2 h1 = __floats2half2_rn(v[k].z * inv, v[k].w * inv);
            *reinterpret_cast<__half2*>(rowp + i)     = h0;
            *reinterpret_cast<__half2*>(rowp + i + 2) = h1;
        }
    }
}

// ---------------------------------------------------------------------------
// Launch
// ---------------------------------------------------------------------------
extern "C" void kernel_launch(void* const* d_in, const int* in_sizes, int n_in,
                              void* d_out, int out_size)
{
    (void)in_sizes; (void)n_in; (void)out_size;
    const float* x  = (const float*)d_in[0];
    const float* Wq = (const float*)d_in[1];
    const float* Wc = (const float*)d_in[2];
    const float* Wk = (const float*)d_in[3];
    const float* Wv = (const float*)d_in[4];
    const float* Wo = (const float*)d_in[5];
    const float* bo = (const float*)d_in[6];
    float* out = (float*)d_out;

    __half *xh, *q, *c, *k, *vt, *y, *p, *wqt, *wct, *wkt, *wvt, *wot;
    float *s;
    cudaGetSymbolAddress((void**)&xh, g_xh);
    cudaGetSymbolAddress((void**)&q,  g_q);
    cudaGetSymbolAddress((void**)&c,  g_c);
    cudaGetSymbolAddress((void**)&k,  g_k);
    cudaGetSymbolAddress((void**)&vt, g_vt);
    cudaGetSymbolAddress((void**)&y,  g_y);
    cudaGetSymbolAddress((void**)&s,  g_s);
    cudaGetSymbolAddress((void**)&p,  g_p);
    cudaGetSymbolAddress((void**)&wqt, g_wqt);
    cudaGetSymbolAddress((void**)&wct, g_wct);
    cudaGetSymbolAddress((void**)&wkt, g_wkt);
    cudaGetSymbolAddress((void**)&wvt, g_wvt);
    cudaGetSymbolAddress((void**)&wot, g_wot);

    const int gemm_smem = NSTAGE * 2 * TILE_H * (int)sizeof(__half);  // 61440 B
    cudaFuncSetAttribute(gemm_mma,
                         cudaFuncAttributeMaxDynamicSharedMemorySize, gemm_smem);

    const float scale = 0.08838834764831845f;   // 1/sqrt(128), folded into WqT

    dim3 tb(32, 8);
    transpose_k<<<dim3(CC / 32, CC / 32), tb>>>(Wq, wqt, CC, CC, scale);
    transpose_k<<<dim3(DL / 32, CC / 32), tb>>>(Wc, wct, CC, DL, 1.f);
    transpose_k<<<dim3(CC / 32, DL / 32), tb>>>(Wk, wkt, DL, CC, 1.f);
    transpose_k<<<dim3(CC / 32, DL / 32), tb>>>(Wv, wvt, DL, CC, 1.f);
    transpose_k<<<dim3(CC / 32, CC / 32), tb>>>(Wo, wot, CC, CC, 1.f);

    conv_half<<<(BT * CC / 4 + 255) / 256, 256>>>(
        (const float4*)x, (__half2*)xh, BT * CC / 4);

    dim3 blk(256);

    // q = xh @ Wq' (scale folded), half out
    gemm_mma<<<dim3(CC / 128, BT / 128, 1), blk, gemm_smem>>>(
        xh, CC, 0, 0, wqt, CC, 0, 0, q, CC, 0, 0, CC, nullptr, 4);
    // c = xh @ Wc, half out
    gemm_mma<<<dim3(DL / 128, BT / 128, 1), blk, gemm_smem>>>(
        xh, CC, 0, 0, wct, CC, 0, 0, c, DL, 0, 0, CC, nullptr, 4);
    // k = c @ Wk, half out
    gemm_mma<<<dim3(CC / 128, BT / 128, 1), blk, gemm_smem>>>(
        c, DL, 0, 0, wkt, DL, 0, 0, k, CC, 0, 0, DL, nullptr, 4);
    // vT = Wv^T . c^T -> vt[CC, BT], half out
    gemm_mma<<<dim3(BT / 128, CC / 128, 1), blk, gemm_smem>>>(
        wvt, DL, 0, 0, c, DL, 0, 0, vt, BT, 0, 0, DL, nullptr, 4);

    // S = Q_h . K_h^T per (b,h)  [causal block skip], fp32 out
    gemm_mma<<<dim3(TT / 128, TT / 128, BHN), blk, gemm_smem>>>(
        q, CC, HSD, (long long)TT * CC,
        k, CC, HSD, (long long)TT * CC,
        s, TT, (long long)TT * TT, (long long)NH * TT * TT,
        HSD, nullptr, 1);

    // softmax: S (fp32) -> P (half)
    softmax_causal<<<dim3(TT, BHN), blk>>>(s, p);

    // O = P . V^T  [causal K limit, heavy blocks first], half out
    gemm_mma<<<dim3(HSD / 128, TT / 128, BHN), blk, gemm_smem>>>(
        p, TT, (long long)TT * TT, (long long)NH * TT * TT,
        vt, BT, (long long)HSD * BT, TT,
        y, CC, HSD, (long long)TT * CC,
        TT, nullptr, 2 | 4 | 8);

    // out = y @ Wo + bo   (fp32 epilogue)
    gemm_mma<<<dim3(CC / 128, BT / 128, 1), blk, gemm_smem>>>(
        y, CC, 0, 0, wot, CC, 0, 0, out, CC, 0, 0, CC, bo, 0);
}